// round 1
// baseline (speedup 1.0000x reference)
#include <cuda_runtime.h>
#include <math.h>

// Problem constants
#define NN 50000
#define EE 300000
#define CC 256            // K*D_OUT
#define NC (NN*CC)        // 12,800,000
#define KH 8
#define N8 (NN*KH)
#define SLOPE 0.2f

// ---------------- scratch (static device allocations) ----------------
__device__ float g_H[4*NC];       // node projections H[t] = feats[t] @ W_node[dt[t]]
__device__ float g_NR[4*NC];      // (1-alpha)*(feats[r]@Wres + bres)  (inherit part)
__device__ float g_CONV[4*NC];    // per-relation conv accumulators
__device__ float g_EL[4*N8];
__device__ float g_ER[4*N8];
__device__ float g_M[4*N8];
__device__ float g_Z[4*N8];
__device__ float g_EDGE[4*EE*KH]; // edge logits, then exp values
__device__ float g_ATTN[4*512];   // rel_feats[r] @ Wr[r], (4, K, 64)
__device__ float g_WCAT[4*256*512]; // [W_node[dt] | Wres[dt]] per relation
__device__ float g_ALPHA[2];      // sigmoid(resw[t])

__device__ __forceinline__ float leaky(float x) { return x >= 0.f ? x : SLOPE*x; }

__device__ __forceinline__ void atomicMaxFloat(float* addr, float val) {
    int* ia = (int*)addr;
    int old = *ia;
    while (__int_as_float(old) < val) {
        int assumed = old;
        old = atomicCAS(ia, assumed, __float_as_int(val));
        if (old == assumed) break;
    }
}

// ---------------- tiny setup kernels ----------------
// attn[r] = rel_feats[r] @ Wr[r]  -> (4, 512)
__global__ void k_attn(const float* __restrict__ rf, const float* __restrict__ Wr) {
    int r = blockIdx.x;          // 4 blocks, 512 threads
    int j = threadIdx.x;
    float acc = 0.f;
    #pragma unroll 8
    for (int d = 0; d < 64; d++) acc += rf[r*64 + d] * Wr[(r*64 + d)*512 + j];
    g_ATTN[r*512 + j] = acc;
}

__global__ void k_alpha(const float* __restrict__ resw) {
    int t = threadIdx.x;
    if (t < 2) g_ALPHA[t] = 1.0f / (1.0f + expf(-resw[t]));
}

// rel_out: (4, 256) appended at d_out + 4*N*C
__global__ void k_relout(const float* __restrict__ rf, const float* __restrict__ Wupd,
                         const float* __restrict__ bupd, float* __restrict__ out) {
    int r = blockIdx.x;
    int o = threadIdx.x;
    float acc = bupd[r*256 + o];
    #pragma unroll 8
    for (int d = 0; d < 64; d++) acc += rf[r*64 + d] * Wupd[(r*64 + d)*256 + o];
    out[(size_t)4*NC + r*256 + o] = acc;
}

// Build concatenated weights per relation: cols 0..255 = W_node[dt], 256..511 = Wres[dt]
__global__ void k_wcat(const float* __restrict__ W_node, const float* __restrict__ Wres) {
    int idx = blockIdx.x * 256 + threadIdx.x;     // 4*256*512 = 524288
    int z = idx >> 17;          // /(256*512)
    int rem = idx & 131071;
    int row = rem >> 9;
    int col = rem & 511;
    int dt = 1 - (z & 1);
    float v = (col < 256) ? W_node[dt*65536 + row*256 + col]
                          : Wres[dt*65536 + row*256 + (col - 256)];
    g_WCAT[idx] = v;
}

// zero CONV, init M=-inf, Z=0
__global__ void k_init() {
    int idx = blockIdx.x * 256 + threadIdx.x;
    if (idx < 4*NC) g_CONV[idx] = 0.f;
    if (idx < 4*N8) { g_M[idx] = -INFINITY; g_Z[idx] = 0.f; }
}

// ---------------- fused GEMM: C[z] = feats[z] @ WCAT[z]  (M=50000, N=512, K=256) ----------------
#define BM 64
#define BN 64
#define BK 16
__global__ __launch_bounds__(256) void k_gemm(const float* __restrict__ feats,
                                              const float* __restrict__ bres) {
    int z = blockIdx.z;
    const float* A = feats + (size_t)z * NC;
    const float* B = g_WCAT + z * 256 * 512;
    int row0 = blockIdx.y * BM;
    int col0 = blockIdx.x * BN;

    __shared__ float As[BK][BM];
    __shared__ float Bs[BK][BN];

    int tid = threadIdx.x;
    int tx = tid & 15, ty = tid >> 4;
    int am = tid >> 2;           // 0..63
    int ak = (tid & 3) * 4;      // 0,4,8,12
    int bk = tid >> 4;           // 0..15
    int bn = (tid & 15) * 4;     // 0..60

    float acc[4][4] = {};

    for (int k0 = 0; k0 < 256; k0 += BK) {
        int gr = row0 + am;
        float4 av = make_float4(0.f,0.f,0.f,0.f);
        if (gr < NN) av = *(const float4*)(A + (size_t)gr*256 + k0 + ak);
        As[ak+0][am] = av.x; As[ak+1][am] = av.y; As[ak+2][am] = av.z; As[ak+3][am] = av.w;
        float4 bv = *(const float4*)(B + (k0 + bk)*512 + col0 + bn);
        *(float4*)&Bs[bk][bn] = bv;
        __syncthreads();
        #pragma unroll
        for (int kk = 0; kk < BK; kk++) {
            float a[4], b[4];
            #pragma unroll
            for (int i = 0; i < 4; i++) a[i] = As[kk][ty + 16*i];
            #pragma unroll
            for (int j = 0; j < 4; j++) b[j] = Bs[kk][tx + 16*j];
            #pragma unroll
            for (int i = 0; i < 4; i++)
                #pragma unroll
                for (int j = 0; j < 4; j++) acc[i][j] += a[i]*b[j];
        }
        __syncthreads();
    }

    int dt = 1 - (z & 1);
    float om = 1.0f - g_ALPHA[dt];
    bool resCol = (col0 >= 256);
    #pragma unroll
    for (int i = 0; i < 4; i++) {
        int rr = row0 + ty + 16*i;
        if (rr >= NN) continue;
        #pragma unroll
        for (int j = 0; j < 4; j++) {
            int cc = col0 + tx + 16*j;
            if (!resCol) {
                g_H[z*NC + rr*256 + cc] = acc[i][j];
            } else {
                int c2 = cc - 256;
                g_NR[z*NC + rr*256 + c2] = om * (acc[i][j] + bres[dt*256 + c2]);
            }
        }
    }
}

// ---------------- per-node attention logits el/er ----------------
// one warp per (t, n). lane l: k = l/4, d = (l%4)*8 + j
__global__ __launch_bounds__(256) void k_elr() {
    int t = blockIdx.y;
    int warp = threadIdx.x >> 5;
    int l = threadIdx.x & 31;
    int n = blockIdx.x * 8 + warp;
    if (n >= NN) return;
    const int REV[4] = {1, 0, 3, 2};
    int rr = REV[t];
    int k = l >> 2;
    int dbase = (l & 3) * 8;

    const float* hrow = g_H + t*NC + n*256 + l*8;
    float4 h0 = *(const float4*)hrow;
    float4 h1 = *(const float4*)(hrow + 4);
    float h[8] = {h0.x,h0.y,h0.z,h0.w,h1.x,h1.y,h1.z,h1.w};

    const float* aL = g_ATTN + rr*512 + k*64 + dbase;
    const float* aR = g_ATTN + t*512 + k*64 + 32 + dbase;
    float pl = 0.f, pr = 0.f;
    #pragma unroll
    for (int j = 0; j < 8; j++) { pl += h[j]*aL[j]; pr += h[j]*aR[j]; }
    pl += __shfl_xor_sync(0xffffffffu, pl, 1);
    pl += __shfl_xor_sync(0xffffffffu, pl, 2);
    pr += __shfl_xor_sync(0xffffffffu, pr, 1);
    pr += __shfl_xor_sync(0xffffffffu, pr, 2);
    if ((l & 3) == 0) {
        g_EL[rr*N8 + n*KH + k] = pl;
        g_ER[t*N8 + n*KH + k] = pr;
    }
}

// ---------------- edge pass A: logits + segment max ----------------
__global__ __launch_bounds__(256) void k_edge_a(
    const int* __restrict__ s0, const int* __restrict__ s1,
    const int* __restrict__ s2, const int* __restrict__ s3,
    const int* __restrict__ d0, const int* __restrict__ d1,
    const int* __restrict__ d2, const int* __restrict__ d3) {
    int i = blockIdx.x * 256 + threadIdx.x;
    if (i >= EE) return;
    int r = blockIdx.y;
    const int* sp = r==0?s0:(r==1?s1:(r==2?s2:s3));
    const int* dp = r==0?d0:(r==1?d1:(r==2?d2:d3));
    int s = sp[i], d = dp[i];
    const float4* elp = (const float4*)(g_EL + r*N8 + s*KH);
    const float4* erp = (const float4*)(g_ER + r*N8 + d*KH);
    float4 l0 = elp[0], l1 = elp[1], r0 = erp[0], r1 = erp[1];
    float e[8] = { leaky(l0.x+r0.x), leaky(l0.y+r0.y), leaky(l0.z+r0.z), leaky(l0.w+r0.w),
                   leaky(l1.x+r1.x), leaky(l1.y+r1.y), leaky(l1.z+r1.z), leaky(l1.w+r1.w) };
    float* eo = g_EDGE + (size_t)r*EE*KH + (size_t)i*KH;
    *(float4*)eo = make_float4(e[0],e[1],e[2],e[3]);
    *(float4*)(eo+4) = make_float4(e[4],e[5],e[6],e[7]);
    float* mb = g_M + r*N8 + d*KH;
    #pragma unroll
    for (int k = 0; k < 8; k++) atomicMaxFloat(mb + k, e[k]);
}

// ---------------- edge pass B: exp + segment sum ----------------
__global__ __launch_bounds__(256) void k_edge_b(
    const int* __restrict__ d0, const int* __restrict__ d1,
    const int* __restrict__ d2, const int* __restrict__ d3) {
    int i = blockIdx.x * 256 + threadIdx.x;
    if (i >= EE) return;
    int r = blockIdx.y;
    const int* dp = r==0?d0:(r==1?d1:(r==2?d2:d3));
    int d = dp[i];
    float* eo = g_EDGE + (size_t)r*EE*KH + (size_t)i*KH;
    float4 e0 = *(float4*)eo, e1 = *(float4*)(eo+4);
    const float4* mp = (const float4*)(g_M + r*N8 + d*KH);
    float4 m0 = mp[0], m1 = mp[1];
    float ex[8] = { __expf(e0.x-m0.x), __expf(e0.y-m0.y), __expf(e0.z-m0.z), __expf(e0.w-m0.w),
                    __expf(e1.x-m1.x), __expf(e1.y-m1.y), __expf(e1.z-m1.z), __expf(e1.w-m1.w) };
    *(float4*)eo = make_float4(ex[0],ex[1],ex[2],ex[3]);
    *(float4*)(eo+4) = make_float4(ex[4],ex[5],ex[6],ex[7]);
    float* zb = g_Z + r*N8 + d*KH;
    #pragma unroll
    for (int k = 0; k < 8; k++) atomicAdd(zb + k, ex[k]);
}

// ---------------- edge pass C: weighted message scatter ----------------
// one warp per (r, edge). lane l handles elements l*8..l*8+7 (k = l/4)
__global__ __launch_bounds__(256) void k_edge_c(
    const int* __restrict__ s0, const int* __restrict__ s1,
    const int* __restrict__ s2, const int* __restrict__ s3,
    const int* __restrict__ d0, const int* __restrict__ d1,
    const int* __restrict__ d2, const int* __restrict__ d3) {
    int r = blockIdx.y;
    int warp = threadIdx.x >> 5;
    int l = threadIdx.x & 31;
    int i = blockIdx.x * 8 + warp;
    if (i >= EE) return;
    const int REV[4] = {1, 0, 3, 2};
    const int* sp = r==0?s0:(r==1?s1:(r==2?s2:s3));
    const int* dp = r==0?d0:(r==1?d1:(r==2?d2:d3));
    int s = sp[i], d = dp[i];
    int k = l >> 2;
    float ex = g_EDGE[(size_t)r*EE*KH + (size_t)i*KH + k];
    float z = g_Z[r*N8 + d*KH + k];
    float a = ex / z;
    const float* hp = g_H + REV[r]*NC + s*256 + l*8;
    float4 h0 = *(const float4*)hp;
    float4 h1 = *(const float4*)(hp + 4);
    float* cb = g_CONV + r*NC + d*256 + l*8;
    atomicAdd(cb+0, a*h0.x); atomicAdd(cb+1, a*h0.y);
    atomicAdd(cb+2, a*h0.z); atomicAdd(cb+3, a*h0.w);
    atomicAdd(cb+4, a*h1.x); atomicAdd(cb+5, a*h1.y);
    atomicAdd(cb+6, a*h1.z); atomicAdd(cb+7, a*h1.w);
}

// ---------------- finalize + cross-relation attention ----------------
// warp per (g, n); g=0 -> relations {0,2} (dtype 1), g=1 -> {1,3} (dtype 0)
__global__ __launch_bounds__(256) void k_cross(const float* __restrict__ rel_attn,
                                               float* __restrict__ out) {
    int g = blockIdx.y;
    int warp = threadIdx.x >> 5;
    int l = threadIdx.x & 31;
    int n = blockIdx.x * 8 + warp;
    if (n >= NN) return;
    int rel0 = g == 0 ? 0 : 1;
    int rel1 = g == 0 ? 2 : 3;
    int dt = 1 - g;
    float alpha = g_ALPHA[dt];
    int off = n*256 + l*8;

    float h0[8], h1[8];
    {
        const float* c0 = g_CONV + rel0*NC + off;
        const float* i0 = g_NR + rel0*NC + off;
        float4 ca = *(const float4*)c0, cb = *(const float4*)(c0+4);
        float4 ia = *(const float4*)i0, ib = *(const float4*)(i0+4);
        float cv[8] = {ca.x,ca.y,ca.z,ca.w,cb.x,cb.y,cb.z,cb.w};
        float iv[8] = {ia.x,ia.y,ia.z,ia.w,ib.x,ib.y,ib.z,ib.w};
        #pragma unroll
        for (int j = 0; j < 8; j++) h0[j] = alpha * fmaxf(cv[j], 0.f) + iv[j];
    }
    {
        const float* c1 = g_CONV + rel1*NC + off;
        const float* i1 = g_NR + rel1*NC + off;
        float4 ca = *(const float4*)c1, cb = *(const float4*)(c1+4);
        float4 ia = *(const float4*)i1, ib = *(const float4*)(i1+4);
        float cv[8] = {ca.x,ca.y,ca.z,ca.w,cb.x,cb.y,cb.z,cb.w};
        float iv[8] = {ia.x,ia.y,ia.z,ia.w,ib.x,ib.y,ib.z,ib.w};
        #pragma unroll
        for (int j = 0; j < 8; j++) h1[j] = alpha * fmaxf(cv[j], 0.f) + iv[j];
    }

    // two output relations share these h's (stack order is always [rel0, rel1])
    #pragma unroll
    for (int oi = 0; oi < 2; oi++) {
        int ro = oi == 0 ? rel0 : rel1;
        const float* ra = rel_attn + ro*256 + l*8;
        float s0 = 0.f, s1 = 0.f;
        #pragma unroll
        for (int j = 0; j < 8; j++) { s0 += h0[j]*ra[j]; s1 += h1[j]*ra[j]; }
        s0 += __shfl_xor_sync(0xffffffffu, s0, 1);
        s0 += __shfl_xor_sync(0xffffffffu, s0, 2);
        s1 += __shfl_xor_sync(0xffffffffu, s1, 1);
        s1 += __shfl_xor_sync(0xffffffffu, s1, 2);
        s0 = leaky(s0); s1 = leaky(s1);
        float mx = fmaxf(s0, s1);
        float w0 = __expf(s0 - mx), w1 = __expf(s1 - mx);
        float inv = 1.0f / (w0 + w1);
        w0 *= inv; w1 *= inv;
        float o[8];
        #pragma unroll
        for (int j = 0; j < 8; j++) o[j] = w0*h0[j] + w1*h1[j];
        float* op = out + (size_t)ro*NC + off;
        *(float4*)op = make_float4(o[0],o[1],o[2],o[3]);
        *(float4*)(op+4) = make_float4(o[4],o[5],o[6],o[7]);
    }
}

// ---------------- launch ----------------
extern "C" void kernel_launch(void* const* d_in, const int* in_sizes, int n_in,
                              void* d_out, int out_size) {
    const float* feats      = (const float*)d_in[0];
    const float* rel_feats  = (const float*)d_in[1];
    const int*   src_rates  = (const int*)d_in[2];
    const int*   dst_rates  = (const int*)d_in[3];
    const int*   src_clicks = (const int*)d_in[4];
    const int*   dst_clicks = (const int*)d_in[5];
    const float* W_node     = (const float*)d_in[6];
    const float* Wr         = (const float*)d_in[7];
    const float* Wres       = (const float*)d_in[8];
    const float* bres       = (const float*)d_in[9];
    const float* resw       = (const float*)d_in[10];
    const float* rel_attn   = (const float*)d_in[11];
    const float* Wupd       = (const float*)d_in[12];
    const float* bupd       = (const float*)d_in[13];
    float* out = (float*)d_out;

    // srcs = [sr, dr, sc, dc], dsts = [dr, sr, dc, sc]
    const int* S0 = src_rates;  const int* S1 = dst_rates;
    const int* S2 = src_clicks; const int* S3 = dst_clicks;
    const int* D0 = dst_rates;  const int* D1 = src_rates;
    const int* D2 = dst_clicks; const int* D3 = src_clicks;

    k_attn<<<4, 512>>>(rel_feats, Wr);
    k_alpha<<<1, 32>>>(resw);
    k_relout<<<4, 256>>>(rel_feats, Wupd, bupd, out);
    k_wcat<<<2048, 256>>>(W_node, Wres);
    k_init<<<(4*NC + 255) / 256, 256>>>();

    dim3 ggrid(512/BN, (NN + BM - 1)/BM, 4);
    k_gemm<<<ggrid, 256>>>(feats, bres);

    k_elr<<<dim3(NN/8, 4), 256>>>();
    k_edge_a<<<dim3((EE + 255)/256, 4), 256>>>(S0,S1,S2,S3, D0,D1,D2,D3);
    k_edge_b<<<dim3((EE + 255)/256, 4), 256>>>(D0,D1,D2,D3);
    k_edge_c<<<dim3(EE/8, 4), 256>>>(S0,S1,S2,S3, D0,D1,D2,D3);
    k_cross<<<dim3(NN/8, 2), 256>>>(rel_attn, out);
}

// round 2
// speedup vs baseline: 1.2761x; 1.2761x over previous
#include <cuda_runtime.h>
#include <math.h>

// Problem constants
#define NN 50000
#define EE 300000
#define CC 256            // K*D_OUT
#define NC (NN*CC)        // 12,800,000
#define KH 8
#define N8 (NN*KH)
#define SLOPE 0.2f

// ---------------- scratch (static device allocations) ----------------
__device__ float g_H[4*NC];       // node projections H[t] = feats[t] @ W_node[dt[t]]
__device__ float g_NR[4*NC];      // (1-alpha)*(feats[r]@Wres + bres)  (inherit part)
__device__ float g_CONV[4*NC];    // per-relation conv accumulators
__device__ float g_EL[4*N8];
__device__ float g_ER[4*N8];
__device__ float g_M[4*N8];
__device__ float g_Z[4*N8];
__device__ float g_EDGE[4*EE*KH]; // edge logits, then exp values
__device__ float g_ATTN[4*512];   // rel_feats[r] @ Wr[r], (4, K, 64)
__device__ float g_WBH[4*256*512]; // tf32-hi of [W_node[dt] | Wres[dt]] per relation
__device__ float g_WBL[4*256*512]; // tf32-lo
__device__ float g_ALPHA[2];      // sigmoid(resw[t])

__device__ __forceinline__ float leaky(float x) { return x >= 0.f ? x : SLOPE*x; }

__device__ __forceinline__ float tf32r(float x) {
    unsigned u; asm("cvt.rna.tf32.f32 %0, %1;" : "=r"(u) : "f"(x));
    return __uint_as_float(u);
}

__device__ __forceinline__ void mma8(float* c, const unsigned* a, const unsigned* b) {
    asm volatile("mma.sync.aligned.m16n8k8.row.col.f32.tf32.tf32.f32 "
        "{%0,%1,%2,%3}, {%4,%5,%6,%7}, {%8,%9}, {%0,%1,%2,%3};"
        : "+f"(c[0]), "+f"(c[1]), "+f"(c[2]), "+f"(c[3])
        : "r"(a[0]), "r"(a[1]), "r"(a[2]), "r"(a[3]), "r"(b[0]), "r"(b[1]));
}

__device__ __forceinline__ void atomicMaxFloat(float* addr, float val) {
    int* ia = (int*)addr;
    int old = *ia;
    while (__int_as_float(old) < val) {
        int assumed = old;
        old = atomicCAS(ia, assumed, __float_as_int(val));
        if (old == assumed) break;
    }
}

// ---------------- tiny setup kernels ----------------
__global__ void k_attn(const float* __restrict__ rf, const float* __restrict__ Wr) {
    int r = blockIdx.x;
    int j = threadIdx.x;
    float acc = 0.f;
    #pragma unroll 8
    for (int d = 0; d < 64; d++) acc += rf[r*64 + d] * Wr[(r*64 + d)*512 + j];
    g_ATTN[r*512 + j] = acc;
}

__global__ void k_alpha(const float* __restrict__ resw) {
    int t = threadIdx.x;
    if (t < 2) g_ALPHA[t] = 1.0f / (1.0f + expf(-resw[t]));
}

__global__ void k_relout(const float* __restrict__ rf, const float* __restrict__ Wupd,
                         const float* __restrict__ bupd, float* __restrict__ out) {
    int r = blockIdx.x;
    int o = threadIdx.x;
    float acc = bupd[r*256 + o];
    #pragma unroll 8
    for (int d = 0; d < 64; d++) acc += rf[r*64 + d] * Wupd[(r*64 + d)*256 + o];
    out[(size_t)4*NC + r*256 + o] = acc;
}

// Build split concatenated weights per relation: cols 0..255 = W_node[dt], 256..511 = Wres[dt]
__global__ void k_wsplit(const float* __restrict__ W_node, const float* __restrict__ Wres) {
    int idx = blockIdx.x * 256 + threadIdx.x;     // 4*256*512 = 524288
    int z = idx >> 17;
    int rem = idx & 131071;
    int row = rem >> 9;
    int col = rem & 511;
    int dt = 1 - (z & 1);
    float v = (col < 256) ? W_node[dt*65536 + row*256 + col]
                          : Wres[dt*65536 + row*256 + (col - 256)];
    float hi = tf32r(v);
    float lo = tf32r(v - hi);
    g_WBH[idx] = hi;
    g_WBL[idx] = lo;
}

__global__ void k_init() {
    int idx = blockIdx.x * 256 + threadIdx.x;
    if (idx < 4*NC) g_CONV[idx] = 0.f;
    if (idx < 4*N8) { g_M[idx] = -INFINITY; g_Z[idx] = 0.f; }
}

// ---------------- tensor-core GEMM (3xTF32): C[z] = feats[z] @ WCAT[z] ----------------
// M=50000, N=512, K=256. CTA: 128x64, BK=16, 128 threads (4 warps of 64x32).
#define GBM 128
#define GBN 64
#define GBK 16
#define APITCH 20
#define BPITCH 68
#define ASZ (128*APITCH)         // 2560 floats per plane
#define BSZ (GBK*BPITCH)         // 1088 floats per plane
#define SMEM_FLOATS (4*ASZ + 4*BSZ)   // 2 buf * 2 planes
#define SMEM_BYTES (SMEM_FLOATS*4)    // 58368

__device__ __forceinline__ void g_loadA(const float* __restrict__ A, int row0, int k0,
                                        int t, float4* a4) {
    #pragma unroll
    for (int i = 0; i < 4; i++) {
        int linear = t + i*128;
        int m = linear >> 2;
        int c4 = (linear & 3) * 4;
        int gr = row0 + m;
        a4[i] = (gr < NN) ? *(const float4*)(A + (size_t)gr*256 + k0 + c4)
                          : make_float4(0.f,0.f,0.f,0.f);
    }
}

__device__ __forceinline__ void g_loadB(const float* __restrict__ Bh, const float* __restrict__ Bl,
                                        int col0, int k0, int t, float4* bh, float4* bl) {
    #pragma unroll
    for (int i = 0; i < 2; i++) {
        int linear = t + i*128;
        int k = linear >> 4;
        int n4 = (linear & 15) * 4;
        bh[i] = *(const float4*)(Bh + (size_t)(k0+k)*512 + col0 + n4);
        bl[i] = *(const float4*)(Bl + (size_t)(k0+k)*512 + col0 + n4);
    }
}

__device__ __forceinline__ void g_storeA(float* As, int buf, int t, const float4* a4) {
    float* base = As + buf*2*ASZ;
    #pragma unroll
    for (int i = 0; i < 4; i++) {
        int linear = t + i*128;
        int m = linear >> 2;
        int c4 = (linear & 3) * 4;
        float4 v = a4[i];
        float4 hi, lo;
        hi.x = tf32r(v.x); lo.x = tf32r(v.x - hi.x);
        hi.y = tf32r(v.y); lo.y = tf32r(v.y - hi.y);
        hi.z = tf32r(v.z); lo.z = tf32r(v.z - hi.z);
        hi.w = tf32r(v.w); lo.w = tf32r(v.w - hi.w);
        *(float4*)(base + m*APITCH + c4) = hi;
        *(float4*)(base + ASZ + m*APITCH + c4) = lo;
    }
}

__device__ __forceinline__ void g_storeB(float* Bs, int buf, int t,
                                         const float4* bh, const float4* bl) {
    float* base = Bs + buf*2*BSZ;
    #pragma unroll
    for (int i = 0; i < 2; i++) {
        int linear = t + i*128;
        int k = linear >> 4;
        int n4 = (linear & 15) * 4;
        *(float4*)(base + k*BPITCH + n4) = bh[i];
        *(float4*)(base + BSZ + k*BPITCH + n4) = bl[i];
    }
}

__global__ __launch_bounds__(128, 3) void k_gemm_tc(const float* __restrict__ feats,
                                                    const float* __restrict__ bres) {
    extern __shared__ float sm[];
    float* As = sm;                // [buf][plane][ASZ]
    float* Bs = sm + 4*ASZ;        // [buf][plane][BSZ]

    int z = blockIdx.z;
    const float* A  = feats + (size_t)z * NC;
    const float* Bh = g_WBH + (size_t)z * (256*512);
    const float* Bl = g_WBL + (size_t)z * (256*512);
    int row0 = blockIdx.y * GBM;
    int col0 = blockIdx.x * GBN;
    int t = threadIdx.x;
    int lane = t & 31, wid = t >> 5;
    int wm = (wid & 1) * 64;
    int wn = (wid >> 1) * 32;
    int lr = lane >> 2;           // 0..7
    int lc = lane & 3;            // 0..3

    float c[4][4][4];
    #pragma unroll
    for (int mi = 0; mi < 4; mi++)
        #pragma unroll
        for (int ni = 0; ni < 4; ni++)
            #pragma unroll
            for (int q = 0; q < 4; q++) c[mi][ni][q] = 0.f;

    float4 aP[4], bhP[2], blP[2];
    g_loadA(A, row0, 0, t, aP);
    g_loadB(Bh, Bl, col0, 0, t, bhP, blP);
    g_storeA(As, 0, t, aP);
    g_storeB(Bs, 0, t, bhP, blP);
    __syncthreads();

    #pragma unroll 1
    for (int kt = 0; kt < 16; kt++) {
        int nxt = kt + 1;
        if (nxt < 16) {
            g_loadA(A, row0, nxt*GBK, t, aP);
            g_loadB(Bh, Bl, col0, nxt*GBK, t, bhP, blP);
        }
        int buf = kt & 1;
        const float* Ab = As + buf*2*ASZ;
        const float* Bb = Bs + buf*2*BSZ;

        #pragma unroll
        for (int ks = 0; ks < 2; ks++) {
            int kk = ks * 8;
            unsigned af[4][2][4];
            #pragma unroll
            for (int mi = 0; mi < 4; mi++) {
                const float* p = Ab + (wm + mi*16 + lr)*APITCH + kk + lc;
                af[mi][0][0] = __float_as_uint(p[0]);
                af[mi][0][1] = __float_as_uint(p[8*APITCH]);
                af[mi][0][2] = __float_as_uint(p[4]);
                af[mi][0][3] = __float_as_uint(p[8*APITCH + 4]);
                const float* pl = p + ASZ;
                af[mi][1][0] = __float_as_uint(pl[0]);
                af[mi][1][1] = __float_as_uint(pl[8*APITCH]);
                af[mi][1][2] = __float_as_uint(pl[4]);
                af[mi][1][3] = __float_as_uint(pl[8*APITCH + 4]);
            }
            unsigned bf[4][2][2];
            #pragma unroll
            for (int ni = 0; ni < 4; ni++) {
                const float* p = Bb + (kk + lc)*BPITCH + wn + ni*8 + lr;
                bf[ni][0][0] = __float_as_uint(p[0]);
                bf[ni][0][1] = __float_as_uint(p[4*BPITCH]);
                const float* pl = p + BSZ;
                bf[ni][1][0] = __float_as_uint(pl[0]);
                bf[ni][1][1] = __float_as_uint(pl[4*BPITCH]);
            }
            #pragma unroll
            for (int mi = 0; mi < 4; mi++)
                #pragma unroll
                for (int ni = 0; ni < 4; ni++) {
                    mma8(c[mi][ni], af[mi][0], bf[ni][0]);  // hi*hi
                    mma8(c[mi][ni], af[mi][0], bf[ni][1]);  // hi*lo
                    mma8(c[mi][ni], af[mi][1], bf[ni][0]);  // lo*hi
                }
        }
        if (nxt < 16) {
            g_storeA(As, nxt & 1, t, aP);
            g_storeB(Bs, nxt & 1, t, bhP, blP);
        }
        __syncthreads();
    }

    // epilogue
    int dt = 1 - (z & 1);
    bool isH = (col0 < 256);
    float om = 1.0f - g_ALPHA[dt];
    #pragma unroll
    for (int mi = 0; mi < 4; mi++) {
        int r0 = row0 + wm + mi*16 + lr;
        #pragma unroll
        for (int ni = 0; ni < 4; ni++) {
            int col = col0 + wn + ni*8 + 2*lc;
            if (isH) {
                if (r0 < NN)
                    *(float2*)(g_H + (size_t)z*NC + (size_t)r0*256 + col) =
                        make_float2(c[mi][ni][0], c[mi][ni][1]);
                if (r0 + 8 < NN)
                    *(float2*)(g_H + (size_t)z*NC + (size_t)(r0+8)*256 + col) =
                        make_float2(c[mi][ni][2], c[mi][ni][3]);
            } else {
                int c2 = col - 256;
                float b0 = bres[dt*256 + c2], b1 = bres[dt*256 + c2 + 1];
                if (r0 < NN)
                    *(float2*)(g_NR + (size_t)z*NC + (size_t)r0*256 + c2) =
                        make_float2(om*(c[mi][ni][0] + b0), om*(c[mi][ni][1] + b1));
                if (r0 + 8 < NN)
                    *(float2*)(g_NR + (size_t)z*NC + (size_t)(r0+8)*256 + c2) =
                        make_float2(om*(c[mi][ni][2] + b0), om*(c[mi][ni][3] + b1));
            }
        }
    }
}

// ---------------- per-node attention logits el/er ----------------
__global__ __launch_bounds__(256) void k_elr() {
    int t = blockIdx.y;
    int warp = threadIdx.x >> 5;
    int l = threadIdx.x & 31;
    int n = blockIdx.x * 8 + warp;
    if (n >= NN) return;
    const int REV[4] = {1, 0, 3, 2};
    int rr = REV[t];
    int k = l >> 2;
    int dbase = (l & 3) * 8;

    const float* hrow = g_H + t*NC + n*256 + l*8;
    float4 h0 = *(const float4*)hrow;
    float4 h1 = *(const float4*)(hrow + 4);
    float h[8] = {h0.x,h0.y,h0.z,h0.w,h1.x,h1.y,h1.z,h1.w};

    const float* aL = g_ATTN + rr*512 + k*64 + dbase;
    const float* aR = g_ATTN + t*512 + k*64 + 32 + dbase;
    float pl = 0.f, pr = 0.f;
    #pragma unroll
    for (int j = 0; j < 8; j++) { pl += h[j]*aL[j]; pr += h[j]*aR[j]; }
    pl += __shfl_xor_sync(0xffffffffu, pl, 1);
    pl += __shfl_xor_sync(0xffffffffu, pl, 2);
    pr += __shfl_xor_sync(0xffffffffu, pr, 1);
    pr += __shfl_xor_sync(0xffffffffu, pr, 2);
    if ((l & 3) == 0) {
        g_EL[rr*N8 + n*KH + k] = pl;
        g_ER[t*N8 + n*KH + k] = pr;
    }
}

// ---------------- edge pass A: logits + segment max ----------------
__global__ __launch_bounds__(256) void k_edge_a(
    const int* __restrict__ s0, const int* __restrict__ s1,
    const int* __restrict__ s2, const int* __restrict__ s3,
    const int* __restrict__ d0, const int* __restrict__ d1,
    const int* __restrict__ d2, const int* __restrict__ d3) {
    int i = blockIdx.x * 256 + threadIdx.x;
    if (i >= EE) return;
    int r = blockIdx.y;
    const int* sp = r==0?s0:(r==1?s1:(r==2?s2:s3));
    const int* dp = r==0?d0:(r==1?d1:(r==2?d2:d3));
    int s = sp[i], d = dp[i];
    const float4* elp = (const float4*)(g_EL + r*N8 + s*KH);
    const float4* erp = (const float4*)(g_ER + r*N8 + d*KH);
    float4 l0 = elp[0], l1 = elp[1], r0 = erp[0], r1 = erp[1];
    float e[8] = { leaky(l0.x+r0.x), leaky(l0.y+r0.y), leaky(l0.z+r0.z), leaky(l0.w+r0.w),
                   leaky(l1.x+r1.x), leaky(l1.y+r1.y), leaky(l1.z+r1.z), leaky(l1.w+r1.w) };
    float* eo = g_EDGE + (size_t)r*EE*KH + (size_t)i*KH;
    *(float4*)eo = make_float4(e[0],e[1],e[2],e[3]);
    *(float4*)(eo+4) = make_float4(e[4],e[5],e[6],e[7]);
    float* mb = g_M + r*N8 + d*KH;
    #pragma unroll
    for (int k = 0; k < 8; k++) atomicMaxFloat(mb + k, e[k]);
}

// ---------------- edge pass B: exp + segment sum ----------------
__global__ __launch_bounds__(256) void k_edge_b(
    const int* __restrict__ d0, const int* __restrict__ d1,
    const int* __restrict__ d2, const int* __restrict__ d3) {
    int i = blockIdx.x * 256 + threadIdx.x;
    if (i >= EE) return;
    int r = blockIdx.y;
    const int* dp = r==0?d0:(r==1?d1:(r==2?d2:d3));
    int d = dp[i];
    float* eo = g_EDGE + (size_t)r*EE*KH + (size_t)i*KH;
    float4 e0 = *(float4*)eo, e1 = *(float4*)(eo+4);
    const float4* mp = (const float4*)(g_M + r*N8 + d*KH);
    float4 m0 = mp[0], m1 = mp[1];
    float ex[8] = { __expf(e0.x-m0.x), __expf(e0.y-m0.y), __expf(e0.z-m0.z), __expf(e0.w-m0.w),
                    __expf(e1.x-m1.x), __expf(e1.y-m1.y), __expf(e1.z-m1.z), __expf(e1.w-m1.w) };
    *(float4*)eo = make_float4(ex[0],ex[1],ex[2],ex[3]);
    *(float4*)(eo+4) = make_float4(ex[4],ex[5],ex[6],ex[7]);
    float* zb = g_Z + r*N8 + d*KH;
    #pragma unroll
    for (int k = 0; k < 8; k++) atomicAdd(zb + k, ex[k]);
}

// ---------------- edge pass C: weighted message scatter ----------------
__global__ __launch_bounds__(256) void k_edge_c(
    const int* __restrict__ s0, const int* __restrict__ s1,
    const int* __restrict__ s2, const int* __restrict__ s3,
    const int* __restrict__ d0, const int* __restrict__ d1,
    const int* __restrict__ d2, const int* __restrict__ d3) {
    int r = blockIdx.y;
    int warp = threadIdx.x >> 5;
    int l = threadIdx.x & 31;
    int i = blockIdx.x * 8 + warp;
    if (i >= EE) return;
    const int REV[4] = {1, 0, 3, 2};
    const int* sp = r==0?s0:(r==1?s1:(r==2?s2:s3));
    const int* dp = r==0?d0:(r==1?d1:(r==2?d2:d3));
    int s = sp[i], d = dp[i];
    int k = l >> 2;
    float ex = g_EDGE[(size_t)r*EE*KH + (size_t)i*KH + k];
    float z = g_Z[r*N8 + d*KH + k];
    float a = ex / z;
    const float* hp = g_H + REV[r]*NC + s*256 + l*8;
    float4 h0 = *(const float4*)hp;
    float4 h1 = *(const float4*)(hp + 4);
    float* cb = g_CONV + r*NC + d*256 + l*8;
    atomicAdd(cb+0, a*h0.x); atomicAdd(cb+1, a*h0.y);
    atomicAdd(cb+2, a*h0.z); atomicAdd(cb+3, a*h0.w);
    atomicAdd(cb+4, a*h1.x); atomicAdd(cb+5, a*h1.y);
    atomicAdd(cb+6, a*h1.z); atomicAdd(cb+7, a*h1.w);
}

// ---------------- finalize + cross-relation attention ----------------
__global__ __launch_bounds__(256) void k_cross(const float* __restrict__ rel_attn,
                                               float* __restrict__ out) {
    int g = blockIdx.y;
    int warp = threadIdx.x >> 5;
    int l = threadIdx.x & 31;
    int n = blockIdx.x * 8 + warp;
    if (n >= NN) return;
    int rel0 = g == 0 ? 0 : 1;
    int rel1 = g == 0 ? 2 : 3;
    int dt = 1 - g;
    float alpha = g_ALPHA[dt];
    int off = n*256 + l*8;

    float h0[8], h1[8];
    {
        const float* c0 = g_CONV + rel0*NC + off;
        const float* i0 = g_NR + rel0*NC + off;
        float4 ca = *(const float4*)c0, cb = *(const float4*)(c0+4);
        float4 ia = *(const float4*)i0, ib = *(const float4*)(i0+4);
        float cv[8] = {ca.x,ca.y,ca.z,ca.w,cb.x,cb.y,cb.z,cb.w};
        float iv[8] = {ia.x,ia.y,ia.z,ia.w,ib.x,ib.y,ib.z,ib.w};
        #pragma unroll
        for (int j = 0; j < 8; j++) h0[j] = alpha * fmaxf(cv[j], 0.f) + iv[j];
    }
    {
        const float* c1 = g_CONV + rel1*NC + off;
        const float* i1 = g_NR + rel1*NC + off;
        float4 ca = *(const float4*)c1, cb = *(const float4*)(c1+4);
        float4 ia = *(const float4*)i1, ib = *(const float4*)(i1+4);
        float cv[8] = {ca.x,ca.y,ca.z,ca.w,cb.x,cb.y,cb.z,cb.w};
        float iv[8] = {ia.x,ia.y,ia.z,ia.w,ib.x,ib.y,ib.z,ib.w};
        #pragma unroll
        for (int j = 0; j < 8; j++) h1[j] = alpha * fmaxf(cv[j], 0.f) + iv[j];
    }

    #pragma unroll
    for (int oi = 0; oi < 2; oi++) {
        int ro = oi == 0 ? rel0 : rel1;
        const float* ra = rel_attn + ro*256 + l*8;
        float s0 = 0.f, s1 = 0.f;
        #pragma unroll
        for (int j = 0; j < 8; j++) { s0 += h0[j]*ra[j]; s1 += h1[j]*ra[j]; }
        s0 += __shfl_xor_sync(0xffffffffu, s0, 1);
        s0 += __shfl_xor_sync(0xffffffffu, s0, 2);
        s1 += __shfl_xor_sync(0xffffffffu, s1, 1);
        s1 += __shfl_xor_sync(0xffffffffu, s1, 2);
        s0 = leaky(s0); s1 = leaky(s1);
        float mx = fmaxf(s0, s1);
        float w0 = __expf(s0 - mx), w1 = __expf(s1 - mx);
        float inv = 1.0f / (w0 + w1);
        w0 *= inv; w1 *= inv;
        float o[8];
        #pragma unroll
        for (int j = 0; j < 8; j++) o[j] = w0*h0[j] + w1*h1[j];
        float* op = out + (size_t)ro*NC + off;
        *(float4*)op = make_float4(o[0],o[1],o[2],o[3]);
        *(float4*)(op+4) = make_float4(o[4],o[5],o[6],o[7]);
    }
}

// ---------------- launch ----------------
extern "C" void kernel_launch(void* const* d_in, const int* in_sizes, int n_in,
                              void* d_out, int out_size) {
    const float* feats      = (const float*)d_in[0];
    const float* rel_feats  = (const float*)d_in[1];
    const int*   src_rates  = (const int*)d_in[2];
    const int*   dst_rates  = (const int*)d_in[3];
    const int*   src_clicks = (const int*)d_in[4];
    const int*   dst_clicks = (const int*)d_in[5];
    const float* W_node     = (const float*)d_in[6];
    const float* Wr         = (const float*)d_in[7];
    const float* Wres       = (const float*)d_in[8];
    const float* bres       = (const float*)d_in[9];
    const float* resw       = (const float*)d_in[10];
    const float* rel_attn   = (const float*)d_in[11];
    const float* Wupd       = (const float*)d_in[12];
    const float* bupd       = (const float*)d_in[13];
    float* out = (float*)d_out;

    const int* S0 = src_rates;  const int* S1 = dst_rates;
    const int* S2 = src_clicks; const int* S3 = dst_clicks;
    const int* D0 = dst_rates;  const int* D1 = src_rates;
    const int* D2 = dst_clicks; const int* D3 = src_clicks;

    static int smem_set = 0;
    if (!smem_set) {
        cudaFuncSetAttribute(k_gemm_tc, cudaFuncAttributeMaxDynamicSharedMemorySize, SMEM_BYTES);
        smem_set = 1;
    }

    k_attn<<<4, 512>>>(rel_feats, Wr);
    k_alpha<<<1, 32>>>(resw);
    k_relout<<<4, 256>>>(rel_feats, Wupd, bupd, out);
    k_wsplit<<<2048, 256>>>(W_node, Wres);
    k_init<<<(4*NC + 255) / 256, 256>>>();

    dim3 ggrid(512/GBN, (NN + GBM - 1)/GBM, 4);
    k_gemm_tc<<<ggrid, 128, SMEM_BYTES>>>(feats, bres);

    k_elr<<<dim3(NN/8, 4), 256>>>();
    k_edge_a<<<dim3((EE + 255)/256, 4), 256>>>(S0,S1,S2,S3, D0,D1,D2,D3);
    k_edge_b<<<dim3((EE + 255)/256, 4), 256>>>(D0,D1,D2,D3);
    k_edge_c<<<dim3(EE/8, 4), 256>>>(S0,S1,S2,S3, D0,D1,D2,D3);
    k_cross<<<dim3(NN/8, 2), 256>>>(rel_attn, out);
}

// round 3
// speedup vs baseline: 1.4419x; 1.1300x over previous
#include <cuda_runtime.h>
#include <cuda_bf16.h>
#include <math.h>

// Problem constants
#define NN 50000
#define EE 300000
#define CC 256            // K*D_OUT
#define NC (NN*CC)        // 12,800,000
#define KH 8
#define N8 (NN*KH)
#define SLOPE 0.2f

// ---------------- scratch (static device allocations) ----------------
__device__ float g_H[4*NC];       // node projections H[t] = feats[t] @ W_node[dt[t]]
__device__ float g_NR[4*NC];      // (1-alpha)*(feats[r]@Wres + bres)
__device__ float g_CONV[4*NC];    // per-relation conv accumulators
__device__ float g_EL[4*N8];
__device__ float g_ER[4*N8];
__device__ float g_M[4*N8];
__device__ float g_Z[4*N8];
__device__ float g_EDGE[4*EE*KH];
__device__ float g_ATTN[4*512];
__device__ __nv_bfloat16 g_WTH[4*512*256];  // transposed [z][n][k] split-bf16 hi
__device__ __nv_bfloat16 g_WTL[4*512*256];  // lo
__device__ float g_ALPHA[2];

__device__ __forceinline__ float leaky(float x) { return x >= 0.f ? x : SLOPE*x; }

__device__ __forceinline__ void mma16(float* c, const unsigned* a, const unsigned* b) {
    asm volatile("mma.sync.aligned.m16n8k16.row.col.f32.bf16.bf16.f32 "
        "{%0,%1,%2,%3}, {%4,%5,%6,%7}, {%8,%9}, {%0,%1,%2,%3};"
        : "+f"(c[0]), "+f"(c[1]), "+f"(c[2]), "+f"(c[3])
        : "r"(a[0]), "r"(a[1]), "r"(a[2]), "r"(a[3]), "r"(b[0]), "r"(b[1]));
}

__device__ __forceinline__ void atomicMaxFloat(float* addr, float val) {
    int* ia = (int*)addr;
    int old = *ia;
    while (__int_as_float(old) < val) {
        int assumed = old;
        old = atomicCAS(ia, assumed, __float_as_int(val));
        if (old == assumed) break;
    }
}

__device__ __forceinline__ unsigned pack2(__nv_bfloat16 a, __nv_bfloat16 b) {
    return (unsigned)__bfloat16_as_ushort(a) | ((unsigned)__bfloat16_as_ushort(b) << 16);
}

// ---------------- tiny setup kernels ----------------
__global__ void k_attn(const float* __restrict__ rf, const float* __restrict__ Wr) {
    int r = blockIdx.x;
    int j = threadIdx.x;
    float acc = 0.f;
    #pragma unroll 8
    for (int d = 0; d < 64; d++) acc += rf[r*64 + d] * Wr[(r*64 + d)*512 + j];
    g_ATTN[r*512 + j] = acc;
}

__global__ void k_alpha(const float* __restrict__ resw) {
    int t = threadIdx.x;
    if (t < 2) g_ALPHA[t] = 1.0f / (1.0f + expf(-resw[t]));
}

__global__ void k_relout(const float* __restrict__ rf, const float* __restrict__ Wupd,
                         const float* __restrict__ bupd, float* __restrict__ out) {
    int r = blockIdx.x;
    int o = threadIdx.x;
    float acc = bupd[r*256 + o];
    #pragma unroll 8
    for (int d = 0; d < 64; d++) acc += rf[r*64 + d] * Wupd[(r*64 + d)*256 + o];
    out[(size_t)4*NC + r*256 + o] = acc;
}

// Transposed split-bf16 weights per relation: [z][n(512)][k(256)]
// n<256 -> W_node[dt][k][n]; n>=256 -> Wres[dt][k][n-256]
__global__ void k_wsplit(const float* __restrict__ W_node, const float* __restrict__ Wres) {
    int idx = blockIdx.x * 256 + threadIdx.x;     // 4*512*256 = 524288
    int z = idx >> 17;
    int rem = idx & 131071;
    int k = rem >> 9;       // source-coalesced: n fastest
    int n = rem & 511;
    int dt = 1 - (z & 1);
    float v = (n < 256) ? W_node[dt*65536 + k*256 + n]
                        : Wres[dt*65536 + k*256 + (n - 256)];
    __nv_bfloat16 hi = __float2bfloat16(v);
    __nv_bfloat16 lo = __float2bfloat16(v - __bfloat162float(hi));
    size_t o = (size_t)z*131072 + (size_t)n*256 + k;
    g_WTH[o] = hi;
    g_WTL[o] = lo;
}

__global__ void k_init() {
    int idx = blockIdx.x * 256 + threadIdx.x;
    if (idx < 4*NC) g_CONV[idx] = 0.f;
    if (idx < 4*N8) { g_M[idx] = -INFINITY; g_Z[idx] = 0.f; }
}

// ---------------- tensor-core GEMM (3-term split-bf16) ----------------
// C[z] = feats[z] @ WCAT[z]; M=50000, N=512, K=256.
// CTA 128x128, 256 threads (8 warps, 2x4 -> warp tile 64x32), BK=16, double-buffered.
#define GBM 128
#define GBN 128
#define APW 12                 // words per A row (8 data + 4 pad) -> conflict-free frags
#define BPW 12
#define APLANE (128*APW)       // 1536 words
#define BPLANE (128*BPW)
#define GSMEM_WORDS (4*APLANE + 4*BPLANE)   // 12288
#define GSMEM_BYTES (GSMEM_WORDS*4)          // 49152

__global__ __launch_bounds__(256) void k_gemm_bf16(const float* __restrict__ feats,
                                                   const float* __restrict__ bres) {
    extern __shared__ unsigned smw[];
    unsigned* As = smw;                 // [buf][plane][APLANE]
    unsigned* Bs = smw + 4*APLANE;      // [buf][plane][BPLANE]

    int z = blockIdx.z;
    const float* A = feats + (size_t)z * NC;
    const __nv_bfloat16* BTh = g_WTH + (size_t)z * 131072;
    const __nv_bfloat16* BTl = g_WTL + (size_t)z * 131072;
    int row0 = blockIdx.y * GBM;
    int col0 = blockIdx.x * GBN;
    int t = threadIdx.x;
    int lane = t & 31, wid = t >> 5;
    int wm = (wid & 1) * 64;
    int wn = (wid >> 1) * 32;
    int lr = lane >> 2;      // 0..7
    int lc = lane & 3;       // 0..3

    // staging
    float4 av[2];
    uint4 bh, bl;
    int am[2], aksw[2];
    #pragma unroll
    for (int i = 0; i < 2; i++) {
        int idx = t + i*256;
        am[i] = idx >> 2;
        aksw[i] = (idx & 3) * 2;   // word offset within row
    }
    int bn = t >> 1, bhalf = t & 1;

    float c[4][4][4];
    #pragma unroll
    for (int mi = 0; mi < 4; mi++)
        #pragma unroll
        for (int ni = 0; ni < 4; ni++)
            #pragma unroll
            for (int q = 0; q < 4; q++) c[mi][ni][q] = 0.f;

    // ---- load slab k0 into staging ----
    auto doLoad = [&](int k0) {
        #pragma unroll
        for (int i = 0; i < 2; i++) {
            int gr = row0 + am[i];
            av[i] = (gr < NN) ? *(const float4*)(A + (size_t)gr*256 + k0 + aksw[i]*2)
                              : make_float4(0.f,0.f,0.f,0.f);
        }
        size_t bo = ((size_t)(col0 + bn))*256 + k0 + bhalf*8;
        bh = *(const uint4*)(BTh + bo);
        bl = *(const uint4*)(BTl + bo);
    };
    // ---- store staging into smem buf ----
    auto doStore = [&](int buf) {
        unsigned* ab = As + buf*2*APLANE;
        #pragma unroll
        for (int i = 0; i < 2; i++) {
            float4 v = av[i];
            __nv_bfloat16 hx = __float2bfloat16(v.x);
            __nv_bfloat16 hy = __float2bfloat16(v.y);
            __nv_bfloat16 hz = __float2bfloat16(v.z);
            __nv_bfloat16 hw = __float2bfloat16(v.w);
            unsigned hi0 = pack2(hx, hy), hi1 = pack2(hz, hw);
            unsigned lo0 = pack2(__float2bfloat16(v.x - __bfloat162float(hx)),
                                 __float2bfloat16(v.y - __bfloat162float(hy)));
            unsigned lo1 = pack2(__float2bfloat16(v.z - __bfloat162float(hz)),
                                 __float2bfloat16(v.w - __bfloat162float(hw)));
            int w = am[i]*APW + aksw[i];
            *(uint2*)(ab + w) = make_uint2(hi0, hi1);
            *(uint2*)(ab + APLANE + w) = make_uint2(lo0, lo1);
        }
        unsigned* bb = Bs + buf*2*BPLANE;
        int w = bn*BPW + bhalf*4;
        *(uint4*)(bb + w) = bh;
        *(uint4*)(bb + BPLANE + w) = bl;
    };

    doLoad(0);
    doStore(0);
    __syncthreads();

    #pragma unroll 1
    for (int kt = 0; kt < 16; kt++) {
        if (kt + 1 < 16) doLoad((kt + 1) * 16);
        int buf = kt & 1;
        const unsigned* Ab = As + buf*2*APLANE;
        const unsigned* Bb = Bs + buf*2*BPLANE;

        unsigned af[4][2][4];
        #pragma unroll
        for (int mi = 0; mi < 4; mi++) {
            int base = (wm + mi*16 + lr)*APW + lc;
            af[mi][0][0] = Ab[base];
            af[mi][0][1] = Ab[base + 8*APW];
            af[mi][0][2] = Ab[base + 4];
            af[mi][0][3] = Ab[base + 8*APW + 4];
            const unsigned* Al = Ab + APLANE;
            af[mi][1][0] = Al[base];
            af[mi][1][1] = Al[base + 8*APW];
            af[mi][1][2] = Al[base + 4];
            af[mi][1][3] = Al[base + 8*APW + 4];
        }
        unsigned bfr[4][2][2];
        #pragma unroll
        for (int ni = 0; ni < 4; ni++) {
            int base = (wn + ni*8 + lr)*BPW + lc;
            bfr[ni][0][0] = Bb[base];
            bfr[ni][0][1] = Bb[base + 4];
            const unsigned* Bl = Bb + BPLANE;
            bfr[ni][1][0] = Bl[base];
            bfr[ni][1][1] = Bl[base + 4];
        }
        #pragma unroll
        for (int mi = 0; mi < 4; mi++)
            #pragma unroll
            for (int ni = 0; ni < 4; ni++) {
                mma16(c[mi][ni], af[mi][0], bfr[ni][0]);  // hi*hi
                mma16(c[mi][ni], af[mi][0], bfr[ni][1]);  // hi*lo
                mma16(c[mi][ni], af[mi][1], bfr[ni][0]);  // lo*hi
            }
        if (kt + 1 < 16) doStore((kt + 1) & 1);
        __syncthreads();
    }

    // epilogue
    int dt = 1 - (z & 1);
    float om = 1.0f - g_ALPHA[dt];
    #pragma unroll
    for (int mi = 0; mi < 4; mi++) {
        int r0 = row0 + wm + mi*16 + lr;
        #pragma unroll
        for (int ni = 0; ni < 4; ni++) {
            int col = col0 + wn + ni*8 + 2*lc;
            if (col < 256) {
                if (r0 < NN)
                    *(float2*)(g_H + (size_t)z*NC + (size_t)r0*256 + col) =
                        make_float2(c[mi][ni][0], c[mi][ni][1]);
                if (r0 + 8 < NN)
                    *(float2*)(g_H + (size_t)z*NC + (size_t)(r0+8)*256 + col) =
                        make_float2(c[mi][ni][2], c[mi][ni][3]);
            } else {
                int c2 = col - 256;
                float b0 = bres[dt*256 + c2], b1 = bres[dt*256 + c2 + 1];
                if (r0 < NN)
                    *(float2*)(g_NR + (size_t)z*NC + (size_t)r0*256 + c2) =
                        make_float2(om*(c[mi][ni][0] + b0), om*(c[mi][ni][1] + b1));
                if (r0 + 8 < NN)
                    *(float2*)(g_NR + (size_t)z*NC + (size_t)(r0+8)*256 + c2) =
                        make_float2(om*(c[mi][ni][2] + b0), om*(c[mi][ni][3] + b1));
            }
        }
    }
}

// ---------------- per-node attention logits el/er ----------------
__global__ __launch_bounds__(256) void k_elr() {
    int t = blockIdx.y;
    int warp = threadIdx.x >> 5;
    int l = threadIdx.x & 31;
    int n = blockIdx.x * 8 + warp;
    if (n >= NN) return;
    const int REV[4] = {1, 0, 3, 2};
    int rr = REV[t];
    int k = l >> 2;
    int dbase = (l & 3) * 8;

    const float* hrow = g_H + t*NC + n*256 + l*8;
    float4 h0 = *(const float4*)hrow;
    float4 h1 = *(const float4*)(hrow + 4);
    float h[8] = {h0.x,h0.y,h0.z,h0.w,h1.x,h1.y,h1.z,h1.w};

    const float* aL = g_ATTN + rr*512 + k*64 + dbase;
    const float* aR = g_ATTN + t*512 + k*64 + 32 + dbase;
    float pl = 0.f, pr = 0.f;
    #pragma unroll
    for (int j = 0; j < 8; j++) { pl += h[j]*aL[j]; pr += h[j]*aR[j]; }
    pl += __shfl_xor_sync(0xffffffffu, pl, 1);
    pl += __shfl_xor_sync(0xffffffffu, pl, 2);
    pr += __shfl_xor_sync(0xffffffffu, pr, 1);
    pr += __shfl_xor_sync(0xffffffffu, pr, 2);
    if ((l & 3) == 0) {
        g_EL[rr*N8 + n*KH + k] = pl;
        g_ER[t*N8 + n*KH + k] = pr;
    }
}

// ---------------- edge pass A: logits + segment max ----------------
__global__ __launch_bounds__(256) void k_edge_a(
    const int* __restrict__ s0, const int* __restrict__ s1,
    const int* __restrict__ s2, const int* __restrict__ s3,
    const int* __restrict__ d0, const int* __restrict__ d1,
    const int* __restrict__ d2, const int* __restrict__ d3) {
    int i = blockIdx.x * 256 + threadIdx.x;
    if (i >= EE) return;
    int r = blockIdx.y;
    const int* sp = r==0?s0:(r==1?s1:(r==2?s2:s3));
    const int* dp = r==0?d0:(r==1?d1:(r==2?d2:d3));
    int s = sp[i], d = dp[i];
    const float4* elp = (const float4*)(g_EL + r*N8 + s*KH);
    const float4* erp = (const float4*)(g_ER + r*N8 + d*KH);
    float4 l0 = elp[0], l1 = elp[1], r0 = erp[0], r1 = erp[1];
    float e[8] = { leaky(l0.x+r0.x), leaky(l0.y+r0.y), leaky(l0.z+r0.z), leaky(l0.w+r0.w),
                   leaky(l1.x+r1.x), leaky(l1.y+r1.y), leaky(l1.z+r1.z), leaky(l1.w+r1.w) };
    float* eo = g_EDGE + (size_t)r*EE*KH + (size_t)i*KH;
    *(float4*)eo = make_float4(e[0],e[1],e[2],e[3]);
    *(float4*)(eo+4) = make_float4(e[4],e[5],e[6],e[7]);
    float* mb = g_M + r*N8 + d*KH;
    #pragma unroll
    for (int k = 0; k < 8; k++) atomicMaxFloat(mb + k, e[k]);
}

// ---------------- edge pass B: exp + segment sum ----------------
__global__ __launch_bounds__(256) void k_edge_b(
    const int* __restrict__ d0, const int* __restrict__ d1,
    const int* __restrict__ d2, const int* __restrict__ d3) {
    int i = blockIdx.x * 256 + threadIdx.x;
    if (i >= EE) return;
    int r = blockIdx.y;
    const int* dp = r==0?d0:(r==1?d1:(r==2?d2:d3));
    int d = dp[i];
    float* eo = g_EDGE + (size_t)r*EE*KH + (size_t)i*KH;
    float4 e0 = *(float4*)eo, e1 = *(float4*)(eo+4);
    const float4* mp = (const float4*)(g_M + r*N8 + d*KH);
    float4 m0 = mp[0], m1 = mp[1];
    float ex[8] = { __expf(e0.x-m0.x), __expf(e0.y-m0.y), __expf(e0.z-m0.z), __expf(e0.w-m0.w),
                    __expf(e1.x-m1.x), __expf(e1.y-m1.y), __expf(e1.z-m1.z), __expf(e1.w-m1.w) };
    *(float4*)eo = make_float4(ex[0],ex[1],ex[2],ex[3]);
    *(float4*)(eo+4) = make_float4(ex[4],ex[5],ex[6],ex[7]);
    float* zb = g_Z + r*N8 + d*KH;
    #pragma unroll
    for (int k = 0; k < 8; k++) atomicAdd(zb + k, ex[k]);
}

// ---------------- edge pass C: weighted message scatter ----------------
__global__ __launch_bounds__(256) void k_edge_c(
    const int* __restrict__ s0, const int* __restrict__ s1,
    const int* __restrict__ s2, const int* __restrict__ s3,
    const int* __restrict__ d0, const int* __restrict__ d1,
    const int* __restrict__ d2, const int* __restrict__ d3) {
    int r = blockIdx.y;
    int warp = threadIdx.x >> 5;
    int l = threadIdx.x & 31;
    int i = blockIdx.x * 8 + warp;
    if (i >= EE) return;
    const int REV[4] = {1, 0, 3, 2};
    const int* sp = r==0?s0:(r==1?s1:(r==2?s2:s3));
    const int* dp = r==0?d0:(r==1?d1:(r==2?d2:d3));
    int s = sp[i], d = dp[i];
    int k = l >> 2;
    float ex = g_EDGE[(size_t)r*EE*KH + (size_t)i*KH + k];
    float z = g_Z[r*N8 + d*KH + k];
    float a = ex / z;
    const float* hp = g_H + REV[r]*NC + s*256 + l*8;
    float4 h0 = *(const float4*)hp;
    float4 h1 = *(const float4*)(hp + 4);
    float* cb = g_CONV + r*NC + d*256 + l*8;
    atomicAdd(cb+0, a*h0.x); atomicAdd(cb+1, a*h0.y);
    atomicAdd(cb+2, a*h0.z); atomicAdd(cb+3, a*h0.w);
    atomicAdd(cb+4, a*h1.x); atomicAdd(cb+5, a*h1.y);
    atomicAdd(cb+6, a*h1.z); atomicAdd(cb+7, a*h1.w);
}

// ---------------- finalize + cross-relation attention ----------------
__global__ __launch_bounds__(256) void k_cross(const float* __restrict__ rel_attn,
                                               float* __restrict__ out) {
    int g = blockIdx.y;
    int warp = threadIdx.x >> 5;
    int l = threadIdx.x & 31;
    int n = blockIdx.x * 8 + warp;
    if (n >= NN) return;
    int rel0 = g == 0 ? 0 : 1;
    int rel1 = g == 0 ? 2 : 3;
    int dt = 1 - g;
    float alpha = g_ALPHA[dt];
    int off = n*256 + l*8;

    float h0[8], h1[8];
    {
        const float* c0 = g_CONV + rel0*NC + off;
        const float* i0 = g_NR + rel0*NC + off;
        float4 ca = *(const float4*)c0, cb = *(const float4*)(c0+4);
        float4 ia = *(const float4*)i0, ib = *(const float4*)(i0+4);
        float cv[8] = {ca.x,ca.y,ca.z,ca.w,cb.x,cb.y,cb.z,cb.w};
        float iv[8] = {ia.x,ia.y,ia.z,ia.w,ib.x,ib.y,ib.z,ib.w};
        #pragma unroll
        for (int j = 0; j < 8; j++) h0[j] = alpha * fmaxf(cv[j], 0.f) + iv[j];
    }
    {
        const float* c1 = g_CONV + rel1*NC + off;
        const float* i1 = g_NR + rel1*NC + off;
        float4 ca = *(const float4*)c1, cb = *(const float4*)(c1+4);
        float4 ia = *(const float4*)i1, ib = *(const float4*)(i1+4);
        float cv[8] = {ca.x,ca.y,ca.z,ca.w,cb.x,cb.y,cb.z,cb.w};
        float iv[8] = {ia.x,ia.y,ia.z,ia.w,ib.x,ib.y,ib.z,ib.w};
        #pragma unroll
        for (int j = 0; j < 8; j++) h1[j] = alpha * fmaxf(cv[j], 0.f) + iv[j];
    }

    #pragma unroll
    for (int oi = 0; oi < 2; oi++) {
        int ro = oi == 0 ? rel0 : rel1;
        const float* ra = rel_attn + ro*256 + l*8;
        float s0 = 0.f, s1 = 0.f;
        #pragma unroll
        for (int j = 0; j < 8; j++) { s0 += h0[j]*ra[j]; s1 += h1[j]*ra[j]; }
        s0 += __shfl_xor_sync(0xffffffffu, s0, 1);
        s0 += __shfl_xor_sync(0xffffffffu, s0, 2);
        s1 += __shfl_xor_sync(0xffffffffu, s1, 1);
        s1 += __shfl_xor_sync(0xffffffffu, s1, 2);
        s0 = leaky(s0); s1 = leaky(s1);
        float mx = fmaxf(s0, s1);
        float w0 = __expf(s0 - mx), w1 = __expf(s1 - mx);
        float inv = 1.0f / (w0 + w1);
        w0 *= inv; w1 *= inv;
        float o[8];
        #pragma unroll
        for (int j = 0; j < 8; j++) o[j] = w0*h0[j] + w1*h1[j];
        float* op = out + (size_t)ro*NC + off;
        *(float4*)op = make_float4(o[0],o[1],o[2],o[3]);
        *(float4*)(op+4) = make_float4(o[4],o[5],o[6],o[7]);
    }
}

// ---------------- launch ----------------
extern "C" void kernel_launch(void* const* d_in, const int* in_sizes, int n_in,
                              void* d_out, int out_size) {
    const float* feats      = (const float*)d_in[0];
    const float* rel_feats  = (const float*)d_in[1];
    const int*   src_rates  = (const int*)d_in[2];
    const int*   dst_rates  = (const int*)d_in[3];
    const int*   src_clicks = (const int*)d_in[4];
    const int*   dst_clicks = (const int*)d_in[5];
    const float* W_node     = (const float*)d_in[6];
    const float* Wr         = (const float*)d_in[7];
    const float* Wres       = (const float*)d_in[8];
    const float* bres       = (const float*)d_in[9];
    const float* resw       = (const float*)d_in[10];
    const float* rel_attn   = (const float*)d_in[11];
    const float* Wupd       = (const float*)d_in[12];
    const float* bupd       = (const float*)d_in[13];
    float* out = (float*)d_out;

    const int* S0 = src_rates;  const int* S1 = dst_rates;
    const int* S2 = src_clicks; const int* S3 = dst_clicks;
    const int* D0 = dst_rates;  const int* D1 = src_rates;
    const int* D2 = dst_clicks; const int* D3 = src_clicks;

    static int smem_set = 0;
    if (!smem_set) {
        cudaFuncSetAttribute(k_gemm_bf16, cudaFuncAttributeMaxDynamicSharedMemorySize, GSMEM_BYTES);
        smem_set = 1;
    }

    k_attn<<<4, 512>>>(rel_feats, Wr);
    k_alpha<<<1, 32>>>(resw);
    k_relout<<<4, 256>>>(rel_feats, Wupd, bupd, out);
    k_wsplit<<<2048, 256>>>(W_node, Wres);
    k_init<<<(4*NC + 255) / 256, 256>>>();

    dim3 ggrid(512/GBN, (NN + GBM - 1)/GBM, 4);
    k_gemm_bf16<<<ggrid, 256, GSMEM_BYTES>>>(feats, bres);

    k_elr<<<dim3(NN/8, 4), 256>>>();
    k_edge_a<<<dim3((EE + 255)/256, 4), 256>>>(S0,S1,S2,S3, D0,D1,D2,D3);
    k_edge_b<<<dim3((EE + 255)/256, 4), 256>>>(D0,D1,D2,D3);
    k_edge_c<<<dim3(EE/8, 4), 256>>>(S0,S1,S2,S3, D0,D1,D2,D3);
    k_cross<<<dim3(NN/8, 2), 256>>>(rel_attn, out);
}

// round 4
// speedup vs baseline: 3.3345x; 2.3126x over previous
#include <cuda_runtime.h>
#include <cuda_bf16.h>
#include <math.h>

// Problem constants
#define NN 50000
#define EE 300000
#define CC 256            // K*D_OUT
#define NC (NN*CC)        // 12,800,000
#define KH 8
#define N8 (NN*KH)
#define SLOPE 0.2f

// ---------------- scratch (static device allocations) ----------------
__device__ float g_H[4*NC];       // node projections
__device__ float g_NR[4*NC];      // (1-alpha)*(feats[r]@Wres + bres)
__device__ float g_CONV[4*NC];    // per-relation conv results (written fully by k_conv)
__device__ float g_EL[4*N8];
__device__ float g_ER[4*N8];
__device__ float g_ATTN[4*512];
__device__ __nv_bfloat16 g_WTH[4*512*256];  // transposed [z][n][k] split-bf16 hi
__device__ __nv_bfloat16 g_WTL[4*512*256];  // lo
__device__ float g_ALPHA[2];

// CSR
__device__ int g_DEG[4*NN];
__device__ int g_ROWPTR[4*(NN+1)];
__device__ int g_WOFF[4*NN];
__device__ int g_ESRC[4*EE];

__device__ __forceinline__ float leaky(float x) { return x >= 0.f ? x : SLOPE*x; }

__device__ __forceinline__ void mma16(float* c, const unsigned* a, const unsigned* b) {
    asm volatile("mma.sync.aligned.m16n8k16.row.col.f32.bf16.bf16.f32 "
        "{%0,%1,%2,%3}, {%4,%5,%6,%7}, {%8,%9}, {%0,%1,%2,%3};"
        : "+f"(c[0]), "+f"(c[1]), "+f"(c[2]), "+f"(c[3])
        : "r"(a[0]), "r"(a[1]), "r"(a[2]), "r"(a[3]), "r"(b[0]), "r"(b[1]));
}

__device__ __forceinline__ unsigned pack2(__nv_bfloat16 a, __nv_bfloat16 b) {
    return (unsigned)__bfloat16_as_ushort(a) | ((unsigned)__bfloat16_as_ushort(b) << 16);
}

// ---------------- tiny setup kernels ----------------
__global__ void k_attn(const float* __restrict__ rf, const float* __restrict__ Wr) {
    int r = blockIdx.x;
    int j = threadIdx.x;
    float acc = 0.f;
    #pragma unroll 8
    for (int d = 0; d < 64; d++) acc += rf[r*64 + d] * Wr[(r*64 + d)*512 + j];
    g_ATTN[r*512 + j] = acc;
}

__global__ void k_alpha(const float* __restrict__ resw) {
    int t = threadIdx.x;
    if (t < 2) g_ALPHA[t] = 1.0f / (1.0f + expf(-resw[t]));
}

__global__ void k_relout(const float* __restrict__ rf, const float* __restrict__ Wupd,
                         const float* __restrict__ bupd, float* __restrict__ out) {
    int r = blockIdx.x;
    int o = threadIdx.x;
    float acc = bupd[r*256 + o];
    #pragma unroll 8
    for (int d = 0; d < 64; d++) acc += rf[r*64 + d] * Wupd[(r*64 + d)*256 + o];
    out[(size_t)4*NC + r*256 + o] = acc;
}

__global__ void k_wsplit(const float* __restrict__ W_node, const float* __restrict__ Wres) {
    int idx = blockIdx.x * 256 + threadIdx.x;     // 4*512*256 = 524288
    int z = idx >> 17;
    int rem = idx & 131071;
    int k = rem >> 9;
    int n = rem & 511;
    int dt = 1 - (z & 1);
    float v = (n < 256) ? W_node[dt*65536 + k*256 + n]
                        : Wres[dt*65536 + k*256 + (n - 256)];
    __nv_bfloat16 hi = __float2bfloat16(v);
    __nv_bfloat16 lo = __float2bfloat16(v - __bfloat162float(hi));
    size_t o = (size_t)z*131072 + (size_t)n*256 + k;
    g_WTH[o] = hi;
    g_WTL[o] = lo;
}

// ---------------- CSR build ----------------
__global__ void k_zero_deg() {
    int i = blockIdx.x * 256 + threadIdx.x;
    if (i < 4*NN) g_DEG[i] = 0;
}

__global__ void k_hist(const int* __restrict__ d0, const int* __restrict__ d1,
                       const int* __restrict__ d2, const int* __restrict__ d3) {
    int i = blockIdx.x * 256 + threadIdx.x;
    if (i >= EE) return;
    int r = blockIdx.y;
    const int* dp = r==0?d0:(r==1?d1:(r==2?d2:d3));
    atomicAdd(&g_DEG[r*NN + dp[i]], 1);
}

// per-relation exclusive scan; also writes g_WOFF = rowptr[i]
__global__ __launch_bounds__(1024) void k_scan() {
    int r = blockIdx.x;
    __shared__ int sh[1024];
    __shared__ int carry;
    if (threadIdx.x == 0) carry = 0;
    __syncthreads();
    for (int base = 0; base < NN; base += 1024) {
        int i = base + threadIdx.x;
        int v = (i < NN) ? g_DEG[r*NN + i] : 0;
        sh[threadIdx.x] = v;
        __syncthreads();
        #pragma unroll
        for (int off = 1; off < 1024; off <<= 1) {
            int tv = (threadIdx.x >= off) ? sh[threadIdx.x - off] : 0;
            __syncthreads();
            sh[threadIdx.x] += tv;
            __syncthreads();
        }
        int incl = sh[threadIdx.x];
        if (i < NN) {
            g_ROWPTR[r*(NN+1) + i + 1] = carry + incl;
            g_WOFF[r*NN + i] = carry + incl - v;
        }
        __syncthreads();
        if (threadIdx.x == 1023) carry += sh[1023];
        __syncthreads();
    }
    if (threadIdx.x == 0) g_ROWPTR[r*(NN+1)] = 0;
}

__global__ void k_scatter(const int* __restrict__ s0, const int* __restrict__ s1,
                          const int* __restrict__ s2, const int* __restrict__ s3,
                          const int* __restrict__ d0, const int* __restrict__ d1,
                          const int* __restrict__ d2, const int* __restrict__ d3) {
    int i = blockIdx.x * 256 + threadIdx.x;
    if (i >= EE) return;
    int r = blockIdx.y;
    const int* sp = r==0?s0:(r==1?s1:(r==2?s2:s3));
    const int* dp = r==0?d0:(r==1?d1:(r==2?d2:d3));
    int pos = atomicAdd(&g_WOFF[r*NN + dp[i]], 1);
    g_ESRC[r*EE + pos] = sp[i];
}

// ---------------- tensor-core GEMM (3-term split-bf16) ----------------
#define GBM 128
#define GBN 128
#define APW 12
#define BPW 12
#define APLANE (128*APW)
#define BPLANE (128*BPW)
#define GSMEM_WORDS (4*APLANE + 4*BPLANE)
#define GSMEM_BYTES (GSMEM_WORDS*4)

__global__ __launch_bounds__(256) void k_gemm_bf16(const float* __restrict__ feats,
                                                   const float* __restrict__ bres) {
    extern __shared__ unsigned smw[];
    unsigned* As = smw;
    unsigned* Bs = smw + 4*APLANE;

    int z = blockIdx.z;
    const float* A = feats + (size_t)z * NC;
    const __nv_bfloat16* BTh = g_WTH + (size_t)z * 131072;
    const __nv_bfloat16* BTl = g_WTL + (size_t)z * 131072;
    int row0 = blockIdx.y * GBM;
    int col0 = blockIdx.x * GBN;
    int t = threadIdx.x;
    int lane = t & 31, wid = t >> 5;
    int wm = (wid & 1) * 64;
    int wn = (wid >> 1) * 32;
    int lr = lane >> 2;
    int lc = lane & 3;

    float4 av[2];
    uint4 bh, bl;
    int am[2], aksw[2];
    #pragma unroll
    for (int i = 0; i < 2; i++) {
        int idx = t + i*256;
        am[i] = idx >> 2;
        aksw[i] = (idx & 3) * 2;
    }
    int bn = t >> 1, bhalf = t & 1;

    float c[4][4][4];
    #pragma unroll
    for (int mi = 0; mi < 4; mi++)
        #pragma unroll
        for (int ni = 0; ni < 4; ni++)
            #pragma unroll
            for (int q = 0; q < 4; q++) c[mi][ni][q] = 0.f;

    auto doLoad = [&](int k0) {
        #pragma unroll
        for (int i = 0; i < 2; i++) {
            int gr = row0 + am[i];
            av[i] = (gr < NN) ? *(const float4*)(A + (size_t)gr*256 + k0 + aksw[i]*2)
                              : make_float4(0.f,0.f,0.f,0.f);
        }
        size_t bo = ((size_t)(col0 + bn))*256 + k0 + bhalf*8;
        bh = *(const uint4*)(BTh + bo);
        bl = *(const uint4*)(BTl + bo);
    };
    auto doStore = [&](int buf) {
        unsigned* ab = As + buf*2*APLANE;
        #pragma unroll
        for (int i = 0; i < 2; i++) {
            float4 v = av[i];
            __nv_bfloat16 hx = __float2bfloat16(v.x);
            __nv_bfloat16 hy = __float2bfloat16(v.y);
            __nv_bfloat16 hz = __float2bfloat16(v.z);
            __nv_bfloat16 hw = __float2bfloat16(v.w);
            unsigned hi0 = pack2(hx, hy), hi1 = pack2(hz, hw);
            unsigned lo0 = pack2(__float2bfloat16(v.x - __bfloat162float(hx)),
                                 __float2bfloat16(v.y - __bfloat162float(hy)));
            unsigned lo1 = pack2(__float2bfloat16(v.z - __bfloat162float(hz)),
                                 __float2bfloat16(v.w - __bfloat162float(hw)));
            int w = am[i]*APW + aksw[i];
            *(uint2*)(ab + w) = make_uint2(hi0, hi1);
            *(uint2*)(ab + APLANE + w) = make_uint2(lo0, lo1);
        }
        unsigned* bb = Bs + buf*2*BPLANE;
        int w = bn*BPW + bhalf*4;
        *(uint4*)(bb + w) = bh;
        *(uint4*)(bb + BPLANE + w) = bl;
    };

    doLoad(0);
    doStore(0);
    __syncthreads();

    #pragma unroll 1
    for (int kt = 0; kt < 16; kt++) {
        if (kt + 1 < 16) doLoad((kt + 1) * 16);
        int buf = kt & 1;
        const unsigned* Ab = As + buf*2*APLANE;
        const unsigned* Bb = Bs + buf*2*BPLANE;

        unsigned af[4][2][4];
        #pragma unroll
        for (int mi = 0; mi < 4; mi++) {
            int base = (wm + mi*16 + lr)*APW + lc;
            af[mi][0][0] = Ab[base];
            af[mi][0][1] = Ab[base + 8*APW];
            af[mi][0][2] = Ab[base + 4];
            af[mi][0][3] = Ab[base + 8*APW + 4];
            const unsigned* Al = Ab + APLANE;
            af[mi][1][0] = Al[base];
            af[mi][1][1] = Al[base + 8*APW];
            af[mi][1][2] = Al[base + 4];
            af[mi][1][3] = Al[base + 8*APW + 4];
        }
        unsigned bfr[4][2][2];
        #pragma unroll
        for (int ni = 0; ni < 4; ni++) {
            int base = (wn + ni*8 + lr)*BPW + lc;
            bfr[ni][0][0] = Bb[base];
            bfr[ni][0][1] = Bb[base + 4];
            const unsigned* Bl = Bb + BPLANE;
            bfr[ni][1][0] = Bl[base];
            bfr[ni][1][1] = Bl[base + 4];
        }
        #pragma unroll
        for (int mi = 0; mi < 4; mi++)
            #pragma unroll
            for (int ni = 0; ni < 4; ni++) {
                mma16(c[mi][ni], af[mi][0], bfr[ni][0]);
                mma16(c[mi][ni], af[mi][0], bfr[ni][1]);
                mma16(c[mi][ni], af[mi][1], bfr[ni][0]);
            }
        if (kt + 1 < 16) doStore((kt + 1) & 1);
        __syncthreads();
    }

    int dt = 1 - (z & 1);
    float om = 1.0f - g_ALPHA[dt];
    #pragma unroll
    for (int mi = 0; mi < 4; mi++) {
        int r0 = row0 + wm + mi*16 + lr;
        #pragma unroll
        for (int ni = 0; ni < 4; ni++) {
            int col = col0 + wn + ni*8 + 2*lc;
            if (col < 256) {
                if (r0 < NN)
                    *(float2*)(g_H + (size_t)z*NC + (size_t)r0*256 + col) =
                        make_float2(c[mi][ni][0], c[mi][ni][1]);
                if (r0 + 8 < NN)
                    *(float2*)(g_H + (size_t)z*NC + (size_t)(r0+8)*256 + col) =
                        make_float2(c[mi][ni][2], c[mi][ni][3]);
            } else {
                int c2 = col - 256;
                float b0 = bres[dt*256 + c2], b1 = bres[dt*256 + c2 + 1];
                if (r0 < NN)
                    *(float2*)(g_NR + (size_t)z*NC + (size_t)r0*256 + c2) =
                        make_float2(om*(c[mi][ni][0] + b0), om*(c[mi][ni][1] + b1));
                if (r0 + 8 < NN)
                    *(float2*)(g_NR + (size_t)z*NC + (size_t)(r0+8)*256 + c2) =
                        make_float2(om*(c[mi][ni][2] + b0), om*(c[mi][ni][3] + b1));
            }
        }
    }
}

// ---------------- per-node attention logits el/er ----------------
__global__ __launch_bounds__(256) void k_elr() {
    int t = blockIdx.y;
    int warp = threadIdx.x >> 5;
    int l = threadIdx.x & 31;
    int n = blockIdx.x * 8 + warp;
    if (n >= NN) return;
    const int REV[4] = {1, 0, 3, 2};
    int rr = REV[t];
    int k = l >> 2;
    int dbase = (l & 3) * 8;

    const float* hrow = g_H + t*NC + n*256 + l*8;
    float4 h0 = *(const float4*)hrow;
    float4 h1 = *(const float4*)(hrow + 4);
    float h[8] = {h0.x,h0.y,h0.z,h0.w,h1.x,h1.y,h1.z,h1.w};

    const float* aL = g_ATTN + rr*512 + k*64 + dbase;
    const float* aR = g_ATTN + t*512 + k*64 + 32 + dbase;
    float pl = 0.f, pr = 0.f;
    #pragma unroll
    for (int j = 0; j < 8; j++) { pl += h[j]*aL[j]; pr += h[j]*aR[j]; }
    pl += __shfl_xor_sync(0xffffffffu, pl, 1);
    pl += __shfl_xor_sync(0xffffffffu, pl, 2);
    pr += __shfl_xor_sync(0xffffffffu, pr, 1);
    pr += __shfl_xor_sync(0xffffffffu, pr, 2);
    if ((l & 3) == 0) {
        g_EL[rr*N8 + n*KH + k] = pl;
        g_ER[t*N8 + n*KH + k] = pr;
    }
}

// ---------------- fused CSR conv: softmax + weighted aggregation ----------------
// one warp per (relation, dst node)
__global__ __launch_bounds__(256) void k_conv() {
    int r = blockIdx.y;
    int warp = threadIdx.x >> 5;
    int lane = threadIdx.x & 31;
    int d = blockIdx.x * 8 + warp;
    if (d >= NN) return;
    const int REV[4] = {1, 0, 3, 2};

    int start = g_ROWPTR[r*(NN+1) + d];
    int end   = g_ROWPTR[r*(NN+1) + d + 1];
    float* cb = g_CONV + (size_t)r*NC + (size_t)d*256 + lane*8;

    if (start == end) {
        *(float4*)cb = make_float4(0.f,0.f,0.f,0.f);
        *(float4*)(cb+4) = make_float4(0.f,0.f,0.f,0.f);
        return;
    }
    const int* esrc = g_ESRC + r*EE;
    const float* EL = g_EL + r*N8;

    int k = lane & 7, slot = lane >> 3;
    float er_k = g_ER[r*N8 + d*KH + k];

    float m = -INFINITY;
    for (int j0 = start; j0 < end; j0 += 4) {
        int j = j0 + slot;
        if (j < end) {
            int s = esrc[j];
            float e = leaky(EL[s*KH + k] + er_k);
            m = fmaxf(m, e);
        }
    }
    m = fmaxf(m, __shfl_xor_sync(0xffffffffu, m, 8));
    m = fmaxf(m, __shfl_xor_sync(0xffffffffu, m, 16));

    float z = 0.f;
    for (int j0 = start; j0 < end; j0 += 4) {
        int j = j0 + slot;
        if (j < end) {
            int s = esrc[j];
            float e = leaky(EL[s*KH + k] + er_k);
            z += __expf(e - m);
        }
    }
    z += __shfl_xor_sync(0xffffffffu, z, 8);
    z += __shfl_xor_sync(0xffffffffu, z, 16);
    float rz = 1.0f / z;

    // phase 2: accumulation; lane covers channels [lane*8, lane*8+8), head k2 = lane>>2
    int k2 = lane >> 2;
    float er2 = __shfl_sync(0xffffffffu, er_k, k2);
    float m2  = __shfl_sync(0xffffffffu, m, k2);
    float rz2 = __shfl_sync(0xffffffffu, rz, k2);

    const float* Hp = g_H + (size_t)REV[r]*NC;
    float acc[8] = {0.f,0.f,0.f,0.f,0.f,0.f,0.f,0.f};
    for (int j = start; j < end; j++) {
        int s = esrc[j];
        float el2 = EL[s*KH + k2];
        float a = __expf(leaky(el2 + er2) - m2) * rz2;
        const float* hp = Hp + (size_t)s*256 + lane*8;
        float4 h0 = *(const float4*)hp;
        float4 h1 = *(const float4*)(hp + 4);
        acc[0] += a*h0.x; acc[1] += a*h0.y; acc[2] += a*h0.z; acc[3] += a*h0.w;
        acc[4] += a*h1.x; acc[5] += a*h1.y; acc[6] += a*h1.z; acc[7] += a*h1.w;
    }
    *(float4*)cb = make_float4(acc[0],acc[1],acc[2],acc[3]);
    *(float4*)(cb+4) = make_float4(acc[4],acc[5],acc[6],acc[7]);
}

// ---------------- finalize + cross-relation attention ----------------
__global__ __launch_bounds__(256) void k_cross(const float* __restrict__ rel_attn,
                                               float* __restrict__ out) {
    int g = blockIdx.y;
    int warp = threadIdx.x >> 5;
    int l = threadIdx.x & 31;
    int n = blockIdx.x * 8 + warp;
    if (n >= NN) return;
    int rel0 = g == 0 ? 0 : 1;
    int rel1 = g == 0 ? 2 : 3;
    int dt = 1 - g;
    float alpha = g_ALPHA[dt];
    int off = n*256 + l*8;

    float h0[8], h1[8];
    {
        const float* c0 = g_CONV + rel0*NC + off;
        const float* i0 = g_NR + rel0*NC + off;
        float4 ca = *(const float4*)c0, cb = *(const float4*)(c0+4);
        float4 ia = *(const float4*)i0, ib = *(const float4*)(i0+4);
        float cv[8] = {ca.x,ca.y,ca.z,ca.w,cb.x,cb.y,cb.z,cb.w};
        float iv[8] = {ia.x,ia.y,ia.z,ia.w,ib.x,ib.y,ib.z,ib.w};
        #pragma unroll
        for (int j = 0; j < 8; j++) h0[j] = alpha * fmaxf(cv[j], 0.f) + iv[j];
    }
    {
        const float* c1 = g_CONV + rel1*NC + off;
        const float* i1 = g_NR + rel1*NC + off;
        float4 ca = *(const float4*)c1, cb = *(const float4*)(c1+4);
        float4 ia = *(const float4*)i1, ib = *(const float4*)(i1+4);
        float cv[8] = {ca.x,ca.y,ca.z,ca.w,cb.x,cb.y,cb.z,cb.w};
        float iv[8] = {ia.x,ia.y,ia.z,ia.w,ib.x,ib.y,ib.z,ib.w};
        #pragma unroll
        for (int j = 0; j < 8; j++) h1[j] = alpha * fmaxf(cv[j], 0.f) + iv[j];
    }

    #pragma unroll
    for (int oi = 0; oi < 2; oi++) {
        int ro = oi == 0 ? rel0 : rel1;
        const float* ra = rel_attn + ro*256 + l*8;
        float s0 = 0.f, s1 = 0.f;
        #pragma unroll
        for (int j = 0; j < 8; j++) { s0 += h0[j]*ra[j]; s1 += h1[j]*ra[j]; }
        s0 += __shfl_xor_sync(0xffffffffu, s0, 1);
        s0 += __shfl_xor_sync(0xffffffffu, s0, 2);
        s1 += __shfl_xor_sync(0xffffffffu, s1, 1);
        s1 += __shfl_xor_sync(0xffffffffu, s1, 2);
        s0 = leaky(s0); s1 = leaky(s1);
        float mx = fmaxf(s0, s1);
        float w0 = __expf(s0 - mx), w1 = __expf(s1 - mx);
        float inv = 1.0f / (w0 + w1);
        w0 *= inv; w1 *= inv;
        float o[8];
        #pragma unroll
        for (int j = 0; j < 8; j++) o[j] = w0*h0[j] + w1*h1[j];
        float* op = out + (size_t)ro*NC + off;
        *(float4*)op = make_float4(o[0],o[1],o[2],o[3]);
        *(float4*)(op+4) = make_float4(o[4],o[5],o[6],o[7]);
    }
}

// ---------------- launch ----------------
extern "C" void kernel_launch(void* const* d_in, const int* in_sizes, int n_in,
                              void* d_out, int out_size) {
    const float* feats      = (const float*)d_in[0];
    const float* rel_feats  = (const float*)d_in[1];
    const int*   src_rates  = (const int*)d_in[2];
    const int*   dst_rates  = (const int*)d_in[3];
    const int*   src_clicks = (const int*)d_in[4];
    const int*   dst_clicks = (const int*)d_in[5];
    const float* W_node     = (const float*)d_in[6];
    const float* Wr         = (const float*)d_in[7];
    const float* Wres       = (const float*)d_in[8];
    const float* bres       = (const float*)d_in[9];
    const float* resw       = (const float*)d_in[10];
    const float* rel_attn   = (const float*)d_in[11];
    const float* Wupd       = (const float*)d_in[12];
    const float* bupd       = (const float*)d_in[13];
    float* out = (float*)d_out;

    const int* S0 = src_rates;  const int* S1 = dst_rates;
    const int* S2 = src_clicks; const int* S3 = dst_clicks;
    const int* D0 = dst_rates;  const int* D1 = src_rates;
    const int* D2 = dst_clicks; const int* D3 = src_clicks;

    static int smem_set = 0;
    if (!smem_set) {
        cudaFuncSetAttribute(k_gemm_bf16, cudaFuncAttributeMaxDynamicSharedMemorySize, GSMEM_BYTES);
        smem_set = 1;
    }

    // setup + CSR build
    k_attn<<<4, 512>>>(rel_feats, Wr);
    k_alpha<<<1, 32>>>(resw);
    k_relout<<<4, 256>>>(rel_feats, Wupd, bupd, out);
    k_wsplit<<<2048, 256>>>(W_node, Wres);
    k_zero_deg<<<(4*NN + 255)/256, 256>>>();
    k_hist<<<dim3((EE + 255)/256, 4), 256>>>(D0, D1, D2, D3);
    k_scan<<<4, 1024>>>();
    k_scatter<<<dim3((EE + 255)/256, 4), 256>>>(S0,S1,S2,S3, D0,D1,D2,D3);

    // projections
    dim3 ggrid(512/GBN, (NN + GBM - 1)/GBM, 4);
    k_gemm_bf16<<<ggrid, 256, GSMEM_BYTES>>>(feats, bres);

    // attention + conv + output
    k_elr<<<dim3(NN/8, 4), 256>>>();
    k_conv<<<dim3((NN + 7)/8, 4), 256>>>();
    k_cross<<<dim3(NN/8, 2), 256>>>(rel_attn, out);
}

// round 5
// speedup vs baseline: 3.4082x; 1.0221x over previous
#include <cuda_runtime.h>
#include <cuda_bf16.h>
#include <math.h>

// Problem constants
#define NN 50000
#define EE 300000
#define CC 256            // K*D_OUT
#define NC (NN*CC)        // 12,800,000
#define KH 8
#define N8 (NN*KH)
#define SLOPE 0.2f

// ---------------- scratch (static device allocations) ----------------
__device__ float g_H[4*NC];       // node projections
__device__ float g_NR[4*NC];      // (1-alpha)*(feats[r]@Wres + bres)
__device__ float g_EL[4*N8];
__device__ float g_ER[4*N8];
__device__ float g_ATTN[4*512];
__device__ __nv_bfloat16 g_WTH[4*512*256];  // transposed [z][n][k] split-bf16 hi
__device__ __nv_bfloat16 g_WTL[4*512*256];  // lo
__device__ float g_ALPHA[2];

// CSR
__device__ int g_DEG[4*NN];
__device__ int g_ROWPTR[4*(NN+1)];
__device__ int g_WOFF[4*NN];
__device__ int g_ESRC[4*EE];

__device__ __forceinline__ float leaky(float x) { return x >= 0.f ? x : SLOPE*x; }

__device__ __forceinline__ void mma16(float* c, const unsigned* a, const unsigned* b) {
    asm volatile("mma.sync.aligned.m16n8k16.row.col.f32.bf16.bf16.f32 "
        "{%0,%1,%2,%3}, {%4,%5,%6,%7}, {%8,%9}, {%0,%1,%2,%3};"
        : "+f"(c[0]), "+f"(c[1]), "+f"(c[2]), "+f"(c[3])
        : "r"(a[0]), "r"(a[1]), "r"(a[2]), "r"(a[3]), "r"(b[0]), "r"(b[1]));
}

__device__ __forceinline__ unsigned pack2(__nv_bfloat16 a, __nv_bfloat16 b) {
    return (unsigned)__bfloat16_as_ushort(a) | ((unsigned)__bfloat16_as_ushort(b) << 16);
}

// ---------------- tiny setup kernels ----------------
__global__ void k_attn(const float* __restrict__ rf, const float* __restrict__ Wr) {
    int r = blockIdx.x;
    int j = threadIdx.x;
    float acc = 0.f;
    #pragma unroll 8
    for (int d = 0; d < 64; d++) acc += rf[r*64 + d] * Wr[(r*64 + d)*512 + j];
    g_ATTN[r*512 + j] = acc;
}

__global__ void k_alpha(const float* __restrict__ resw) {
    int t = threadIdx.x;
    if (t < 2) g_ALPHA[t] = 1.0f / (1.0f + expf(-resw[t]));
}

__global__ void k_relout(const float* __restrict__ rf, const float* __restrict__ Wupd,
                         const float* __restrict__ bupd, float* __restrict__ out) {
    int r = blockIdx.x;
    int o = threadIdx.x;
    float acc = bupd[r*256 + o];
    #pragma unroll 8
    for (int d = 0; d < 64; d++) acc += rf[r*64 + d] * Wupd[(r*64 + d)*256 + o];
    out[(size_t)4*NC + r*256 + o] = acc;
}

__global__ void k_wsplit(const float* __restrict__ W_node, const float* __restrict__ Wres) {
    int idx = blockIdx.x * 256 + threadIdx.x;     // 4*512*256 = 524288
    int z = idx >> 17;
    int rem = idx & 131071;
    int k = rem >> 9;
    int n = rem & 511;
    int dt = 1 - (z & 1);
    float v = (n < 256) ? W_node[dt*65536 + k*256 + n]
                        : Wres[dt*65536 + k*256 + (n - 256)];
    __nv_bfloat16 hi = __float2bfloat16(v);
    __nv_bfloat16 lo = __float2bfloat16(v - __bfloat162float(hi));
    size_t o = (size_t)z*131072 + (size_t)n*256 + k;
    g_WTH[o] = hi;
    g_WTL[o] = lo;
}

// ---------------- CSR build ----------------
__global__ void k_zero_deg() {
    int i = blockIdx.x * 256 + threadIdx.x;
    if (i < 4*NN) g_DEG[i] = 0;
}

__global__ void k_hist(const int* __restrict__ d0, const int* __restrict__ d1,
                       const int* __restrict__ d2, const int* __restrict__ d3) {
    int i = blockIdx.x * 256 + threadIdx.x;
    if (i >= EE) return;
    int r = blockIdx.y;
    const int* dp = r==0?d0:(r==1?d1:(r==2?d2:d3));
    atomicAdd(&g_DEG[r*NN + dp[i]], 1);
}

__global__ __launch_bounds__(1024) void k_scan() {
    int r = blockIdx.x;
    __shared__ int sh[1024];
    __shared__ int carry;
    if (threadIdx.x == 0) carry = 0;
    __syncthreads();
    for (int base = 0; base < NN; base += 1024) {
        int i = base + threadIdx.x;
        int v = (i < NN) ? g_DEG[r*NN + i] : 0;
        sh[threadIdx.x] = v;
        __syncthreads();
        #pragma unroll
        for (int off = 1; off < 1024; off <<= 1) {
            int tv = (threadIdx.x >= off) ? sh[threadIdx.x - off] : 0;
            __syncthreads();
            sh[threadIdx.x] += tv;
            __syncthreads();
        }
        int incl = sh[threadIdx.x];
        if (i < NN) {
            g_ROWPTR[r*(NN+1) + i + 1] = carry + incl;
            g_WOFF[r*NN + i] = carry + incl - v;
        }
        __syncthreads();
        if (threadIdx.x == 1023) carry += sh[1023];
        __syncthreads();
    }
    if (threadIdx.x == 0) g_ROWPTR[r*(NN+1)] = 0;
}

__global__ void k_scatter(const int* __restrict__ s0, const int* __restrict__ s1,
                          const int* __restrict__ s2, const int* __restrict__ s3,
                          const int* __restrict__ d0, const int* __restrict__ d1,
                          const int* __restrict__ d2, const int* __restrict__ d3) {
    int i = blockIdx.x * 256 + threadIdx.x;
    if (i >= EE) return;
    int r = blockIdx.y;
    const int* sp = r==0?s0:(r==1?s1:(r==2?s2:s3));
    const int* dp = r==0?d0:(r==1?d1:(r==2?d2:d3));
    int pos = atomicAdd(&g_WOFF[r*NN + dp[i]], 1);
    g_ESRC[r*EE + pos] = sp[i];
}

// ---------------- tensor-core GEMM (3-term split-bf16) ----------------
#define GBM 128
#define GBN 128
#define APW 12
#define BPW 12
#define APLANE (128*APW)
#define BPLANE (128*BPW)
#define GSMEM_WORDS (4*APLANE + 4*BPLANE)
#define GSMEM_BYTES (GSMEM_WORDS*4)

__global__ __launch_bounds__(256) void k_gemm_bf16(const float* __restrict__ feats,
                                                   const float* __restrict__ bres) {
    extern __shared__ unsigned smw[];
    unsigned* As = smw;
    unsigned* Bs = smw + 4*APLANE;

    int z = blockIdx.z;
    const float* A = feats + (size_t)z * NC;
    const __nv_bfloat16* BTh = g_WTH + (size_t)z * 131072;
    const __nv_bfloat16* BTl = g_WTL + (size_t)z * 131072;
    int row0 = blockIdx.y * GBM;
    int col0 = blockIdx.x * GBN;
    int t = threadIdx.x;
    int lane = t & 31, wid = t >> 5;
    int wm = (wid & 1) * 64;
    int wn = (wid >> 1) * 32;
    int lr = lane >> 2;
    int lc = lane & 3;

    float4 av[2];
    uint4 bh, bl;
    int am[2], aksw[2];
    #pragma unroll
    for (int i = 0; i < 2; i++) {
        int idx = t + i*256;
        am[i] = idx >> 2;
        aksw[i] = (idx & 3) * 2;
    }
    int bn = t >> 1, bhalf = t & 1;

    float c[4][4][4];
    #pragma unroll
    for (int mi = 0; mi < 4; mi++)
        #pragma unroll
        for (int ni = 0; ni < 4; ni++)
            #pragma unroll
            for (int q = 0; q < 4; q++) c[mi][ni][q] = 0.f;

    auto doLoad = [&](int k0) {
        #pragma unroll
        for (int i = 0; i < 2; i++) {
            int gr = row0 + am[i];
            av[i] = (gr < NN) ? *(const float4*)(A + (size_t)gr*256 + k0 + aksw[i]*2)
                              : make_float4(0.f,0.f,0.f,0.f);
        }
        size_t bo = ((size_t)(col0 + bn))*256 + k0 + bhalf*8;
        bh = *(const uint4*)(BTh + bo);
        bl = *(const uint4*)(BTl + bo);
    };
    auto doStore = [&](int buf) {
        unsigned* ab = As + buf*2*APLANE;
        #pragma unroll
        for (int i = 0; i < 2; i++) {
            float4 v = av[i];
            __nv_bfloat16 hx = __float2bfloat16(v.x);
            __nv_bfloat16 hy = __float2bfloat16(v.y);
            __nv_bfloat16 hz = __float2bfloat16(v.z);
            __nv_bfloat16 hw = __float2bfloat16(v.w);
            unsigned hi0 = pack2(hx, hy), hi1 = pack2(hz, hw);
            unsigned lo0 = pack2(__float2bfloat16(v.x - __bfloat162float(hx)),
                                 __float2bfloat16(v.y - __bfloat162float(hy)));
            unsigned lo1 = pack2(__float2bfloat16(v.z - __bfloat162float(hz)),
                                 __float2bfloat16(v.w - __bfloat162float(hw)));
            int w = am[i]*APW + aksw[i];
            *(uint2*)(ab + w) = make_uint2(hi0, hi1);
            *(uint2*)(ab + APLANE + w) = make_uint2(lo0, lo1);
        }
        unsigned* bb = Bs + buf*2*BPLANE;
        int w = bn*BPW + bhalf*4;
        *(uint4*)(bb + w) = bh;
        *(uint4*)(bb + BPLANE + w) = bl;
    };

    doLoad(0);
    doStore(0);
    __syncthreads();

    #pragma unroll 1
    for (int kt = 0; kt < 16; kt++) {
        if (kt + 1 < 16) doLoad((kt + 1) * 16);
        int buf = kt & 1;
        const unsigned* Ab = As + buf*2*APLANE;
        const unsigned* Bb = Bs + buf*2*BPLANE;

        unsigned af[4][2][4];
        #pragma unroll
        for (int mi = 0; mi < 4; mi++) {
            int base = (wm + mi*16 + lr)*APW + lc;
            af[mi][0][0] = Ab[base];
            af[mi][0][1] = Ab[base + 8*APW];
            af[mi][0][2] = Ab[base + 4];
            af[mi][0][3] = Ab[base + 8*APW + 4];
            const unsigned* Al = Ab + APLANE;
            af[mi][1][0] = Al[base];
            af[mi][1][1] = Al[base + 8*APW];
            af[mi][1][2] = Al[base + 4];
            af[mi][1][3] = Al[base + 8*APW + 4];
        }
        unsigned bfr[4][2][2];
        #pragma unroll
        for (int ni = 0; ni < 4; ni++) {
            int base = (wn + ni*8 + lr)*BPW + lc;
            bfr[ni][0][0] = Bb[base];
            bfr[ni][0][1] = Bb[base + 4];
            const unsigned* Bl = Bb + BPLANE;
            bfr[ni][1][0] = Bl[base];
            bfr[ni][1][1] = Bl[base + 4];
        }
        #pragma unroll
        for (int mi = 0; mi < 4; mi++)
            #pragma unroll
            for (int ni = 0; ni < 4; ni++) {
                mma16(c[mi][ni], af[mi][0], bfr[ni][0]);
                mma16(c[mi][ni], af[mi][0], bfr[ni][1]);
                mma16(c[mi][ni], af[mi][1], bfr[ni][0]);
            }
        if (kt + 1 < 16) doStore((kt + 1) & 1);
        __syncthreads();
    }

    int dt = 1 - (z & 1);
    float om = 1.0f - g_ALPHA[dt];
    #pragma unroll
    for (int mi = 0; mi < 4; mi++) {
        int r0 = row0 + wm + mi*16 + lr;
        #pragma unroll
        for (int ni = 0; ni < 4; ni++) {
            int col = col0 + wn + ni*8 + 2*lc;
            if (col < 256) {
                if (r0 < NN)
                    *(float2*)(g_H + (size_t)z*NC + (size_t)r0*256 + col) =
                        make_float2(c[mi][ni][0], c[mi][ni][1]);
                if (r0 + 8 < NN)
                    *(float2*)(g_H + (size_t)z*NC + (size_t)(r0+8)*256 + col) =
                        make_float2(c[mi][ni][2], c[mi][ni][3]);
            } else {
                int c2 = col - 256;
                float b0 = bres[dt*256 + c2], b1 = bres[dt*256 + c2 + 1];
                if (r0 < NN)
                    *(float2*)(g_NR + (size_t)z*NC + (size_t)r0*256 + c2) =
                        make_float2(om*(c[mi][ni][0] + b0), om*(c[mi][ni][1] + b1));
                if (r0 + 8 < NN)
                    *(float2*)(g_NR + (size_t)z*NC + (size_t)(r0+8)*256 + c2) =
                        make_float2(om*(c[mi][ni][2] + b0), om*(c[mi][ni][3] + b1));
            }
        }
    }
}

// ---------------- per-node attention logits el/er ----------------
__global__ __launch_bounds__(256) void k_elr() {
    int t = blockIdx.y;
    int warp = threadIdx.x >> 5;
    int l = threadIdx.x & 31;
    int n = blockIdx.x * 8 + warp;
    if (n >= NN) return;
    const int REV[4] = {1, 0, 3, 2};
    int rr = REV[t];
    int k = l >> 2;
    int dbase = (l & 3) * 8;

    const float* hrow = g_H + t*NC + n*256 + l*8;
    float4 h0 = *(const float4*)hrow;
    float4 h1 = *(const float4*)(hrow + 4);
    float h[8] = {h0.x,h0.y,h0.z,h0.w,h1.x,h1.y,h1.z,h1.w};

    const float* aL = g_ATTN + rr*512 + k*64 + dbase;
    const float* aR = g_ATTN + t*512 + k*64 + 32 + dbase;
    float pl = 0.f, pr = 0.f;
    #pragma unroll
    for (int j = 0; j < 8; j++) { pl += h[j]*aL[j]; pr += h[j]*aR[j]; }
    pl += __shfl_xor_sync(0xffffffffu, pl, 1);
    pl += __shfl_xor_sync(0xffffffffu, pl, 2);
    pr += __shfl_xor_sync(0xffffffffu, pr, 1);
    pr += __shfl_xor_sync(0xffffffffu, pr, 2);
    if ((l & 3) == 0) {
        g_EL[rr*N8 + n*KH + k] = pl;
        g_ER[t*N8 + n*KH + k] = pr;
    }
}

// ---------------- fused conv + residual + cross-relation attention ----------------
// one warp per (group g, node n); computes both relations' conv in registers.
__global__ __launch_bounds__(256) void k_convcross(const float* __restrict__ rel_attn,
                                                   float* __restrict__ out) {
    int g = blockIdx.y;
    int warp = threadIdx.x >> 5;
    int lane = threadIdx.x & 31;
    int n = blockIdx.x * 8 + warp;
    if (n >= NN) return;
    const int REV[4] = {1, 0, 3, 2};
    int rel[2]; rel[0] = (g == 0) ? 0 : 1; rel[1] = (g == 0) ? 2 : 3;
    int dt = 1 - g;
    float alpha = g_ALPHA[dt];
    int off = n*256 + lane*8;

    float h[2][8];
    #pragma unroll
    for (int q = 0; q < 2; q++) {
        int r = rel[q];
        int start = g_ROWPTR[r*(NN+1) + n];
        int end   = g_ROWPTR[r*(NN+1) + n + 1];
        float acc[8] = {0.f,0.f,0.f,0.f,0.f,0.f,0.f,0.f};
        if (start < end) {
            const int* esrc = g_ESRC + r*EE;
            const float* EL = g_EL + r*N8;
            int k = lane & 7, slot = lane >> 3;
            float er_k = g_ER[r*N8 + n*KH + k];

            // online softmax stats over this node's edges (4 slots in parallel)
            float m = -INFINITY, zz = 0.f;
            for (int j0 = start; j0 < end; j0 += 4) {
                int j = j0 + slot;
                if (j < end) {
                    float e = leaky(EL[esrc[j]*KH + k] + er_k);
                    float nm = fmaxf(m, e);
                    zz = zz * __expf(m - nm) + __expf(e - nm);
                    m = nm;
                }
            }
            // combine (m, zz) across the 4 slots
            #pragma unroll
            for (int o2 = 8; o2 <= 16; o2 <<= 1) {
                float mo = __shfl_xor_sync(0xffffffffu, m, o2);
                float zo = __shfl_xor_sync(0xffffffffu, zz, o2);
                float nm = fmaxf(m, mo);
                float za = (zz > 0.f) ? zz * __expf(m - nm) : 0.f;
                float zb = (zo > 0.f) ? zo * __expf(mo - nm) : 0.f;
                zz = za + zb; m = nm;
            }
            float rz = 1.0f / zz;

            // accumulate: lane covers channels [lane*8, lane*8+8), head k2 = lane>>2
            int k2 = lane >> 2;
            float er2 = __shfl_sync(0xffffffffu, er_k, k2);
            float m2  = __shfl_sync(0xffffffffu, m, k2);
            float rz2 = __shfl_sync(0xffffffffu, rz, k2);
            const float* Hp = g_H + (size_t)REV[r]*NC;
            for (int j = start; j < end; j++) {
                int s = esrc[j];
                float a = __expf(leaky(EL[s*KH + k2] + er2) - m2) * rz2;
                const float* hp = Hp + (size_t)s*256 + lane*8;
                float4 v0 = *(const float4*)hp;
                float4 v1 = *(const float4*)(hp + 4);
                acc[0] += a*v0.x; acc[1] += a*v0.y; acc[2] += a*v0.z; acc[3] += a*v0.w;
                acc[4] += a*v1.x; acc[5] += a*v1.y; acc[6] += a*v1.z; acc[7] += a*v1.w;
            }
        }
        const float* ip = g_NR + (size_t)r*NC + off;
        float4 ia = *(const float4*)ip;
        float4 ib = *(const float4*)(ip + 4);
        float iv[8] = {ia.x,ia.y,ia.z,ia.w,ib.x,ib.y,ib.z,ib.w};
        #pragma unroll
        for (int j = 0; j < 8; j++) h[q][j] = alpha * fmaxf(acc[j], 0.f) + iv[j];
    }

    // cross-relation attention (outputs for rel[0] and rel[1] share the h stack)
    #pragma unroll
    for (int oi = 0; oi < 2; oi++) {
        int ro = rel[oi];
        const float* ra = rel_attn + ro*256 + lane*8;
        float s0 = 0.f, s1 = 0.f;
        #pragma unroll
        for (int j = 0; j < 8; j++) { s0 += h[0][j]*ra[j]; s1 += h[1][j]*ra[j]; }
        s0 += __shfl_xor_sync(0xffffffffu, s0, 1);
        s0 += __shfl_xor_sync(0xffffffffu, s0, 2);
        s1 += __shfl_xor_sync(0xffffffffu, s1, 1);
        s1 += __shfl_xor_sync(0xffffffffu, s1, 2);
        s0 = leaky(s0); s1 = leaky(s1);
        float mx = fmaxf(s0, s1);
        float w0 = __expf(s0 - mx), w1 = __expf(s1 - mx);
        float inv = 1.0f / (w0 + w1);
        w0 *= inv; w1 *= inv;
        float o[8];
        #pragma unroll
        for (int j = 0; j < 8; j++) o[j] = w0*h[0][j] + w1*h[1][j];
        float* op = out + (size_t)ro*NC + off;
        *(float4*)op = make_float4(o[0],o[1],o[2],o[3]);
        *(float4*)(op+4) = make_float4(o[4],o[5],o[6],o[7]);
    }
}

// ---------------- launch ----------------
extern "C" void kernel_launch(void* const* d_in, const int* in_sizes, int n_in,
                              void* d_out, int out_size) {
    const float* feats      = (const float*)d_in[0];
    const float* rel_feats  = (const float*)d_in[1];
    const int*   src_rates  = (const int*)d_in[2];
    const int*   dst_rates  = (const int*)d_in[3];
    const int*   src_clicks = (const int*)d_in[4];
    const int*   dst_clicks = (const int*)d_in[5];
    const float* W_node     = (const float*)d_in[6];
    const float* Wr         = (const float*)d_in[7];
    const float* Wres       = (const float*)d_in[8];
    const float* bres       = (const float*)d_in[9];
    const float* resw       = (const float*)d_in[10];
    const float* rel_attn   = (const float*)d_in[11];
    const float* Wupd       = (const float*)d_in[12];
    const float* bupd       = (const float*)d_in[13];
    float* out = (float*)d_out;

    const int* S0 = src_rates;  const int* S1 = dst_rates;
    const int* S2 = src_clicks; const int* S3 = dst_clicks;
    const int* D0 = dst_rates;  const int* D1 = src_rates;
    const int* D2 = dst_clicks; const int* D3 = src_clicks;

    static int smem_set = 0;
    if (!smem_set) {
        cudaFuncSetAttribute(k_gemm_bf16, cudaFuncAttributeMaxDynamicSharedMemorySize, GSMEM_BYTES);
        smem_set = 1;
    }

    // setup + CSR build
    k_attn<<<4, 512>>>(rel_feats, Wr);
    k_alpha<<<1, 32>>>(resw);
    k_relout<<<4, 256>>>(rel_feats, Wupd, bupd, out);
    k_wsplit<<<2048, 256>>>(W_node, Wres);
    k_zero_deg<<<(4*NN + 255)/256, 256>>>();
    k_hist<<<dim3((EE + 255)/256, 4), 256>>>(D0, D1, D2, D3);
    k_scan<<<4, 1024>>>();
    k_scatter<<<dim3((EE + 255)/256, 4), 256>>>(S0,S1,S2,S3, D0,D1,D2,D3);

    // projections
    dim3 ggrid(512/GBN, (NN + GBM - 1)/GBM, 4);
    k_gemm_bf16<<<ggrid, 256, GSMEM_BYTES>>>(feats, bres);

    // attention + fused conv/cross
    k_elr<<<dim3(NN/8, 4), 256>>>();
    k_convcross<<<dim3((NN + 7)/8, 2), 256>>>(rel_attn, out);
}

// round 6
// speedup vs baseline: 3.4352x; 1.0079x over previous
#include <cuda_runtime.h>
#include <cuda_bf16.h>
#include <math.h>

// Problem constants
#define NN 50000
#define EE 300000
#define CC 256            // K*D_OUT
#define NC (NN*CC)        // 12,800,000
#define KH 8
#define N8 (NN*KH)
#define SLOPE 0.2f

// ---------------- scratch (static device allocations) ----------------
__device__ float g_H[4*NC];       // node projections
__device__ float g_NR[4*NC];      // (1-alpha)*(feats[r]@Wres + bres)
__device__ float g_EL[4*N8];
__device__ float g_ER[4*N8];
__device__ float g_ATTN[4*512];
__device__ __nv_bfloat16 g_WTH[4*512*256];  // transposed [z][n][k] split-bf16 hi
__device__ __nv_bfloat16 g_WTL[4*512*256];  // lo
__device__ float g_ALPHA[2];

// CSR
__device__ int g_DEG[4*NN];
__device__ int g_ROWPTR[4*(NN+1)];
__device__ int g_WOFF[4*NN];
__device__ int g_ESRC[4*EE];

__device__ __forceinline__ float leaky(float x) { return x >= 0.f ? x : SLOPE*x; }

__device__ __forceinline__ void mma16(float* c, const unsigned* a, const unsigned* b) {
    asm volatile("mma.sync.aligned.m16n8k16.row.col.f32.bf16.bf16.f32 "
        "{%0,%1,%2,%3}, {%4,%5,%6,%7}, {%8,%9}, {%0,%1,%2,%3};"
        : "+f"(c[0]), "+f"(c[1]), "+f"(c[2]), "+f"(c[3])
        : "r"(a[0]), "r"(a[1]), "r"(a[2]), "r"(a[3]), "r"(b[0]), "r"(b[1]));
}

__device__ __forceinline__ unsigned pack2(__nv_bfloat16 a, __nv_bfloat16 b) {
    return (unsigned)__bfloat16_as_ushort(a) | ((unsigned)__bfloat16_as_ushort(b) << 16);
}

// ---------------- tiny setup kernels ----------------
__global__ void k_attn(const float* __restrict__ rf, const float* __restrict__ Wr) {
    int r = blockIdx.x;
    int j = threadIdx.x;
    float acc = 0.f;
    #pragma unroll 8
    for (int d = 0; d < 64; d++) acc += rf[r*64 + d] * Wr[(r*64 + d)*512 + j];
    g_ATTN[r*512 + j] = acc;
}

__global__ void k_alpha(const float* __restrict__ resw) {
    int t = threadIdx.x;
    if (t < 2) g_ALPHA[t] = 1.0f / (1.0f + expf(-resw[t]));
}

__global__ void k_relout(const float* __restrict__ rf, const float* __restrict__ Wupd,
                         const float* __restrict__ bupd, float* __restrict__ out) {
    int r = blockIdx.x;
    int o = threadIdx.x;
    float acc = bupd[r*256 + o];
    #pragma unroll 8
    for (int d = 0; d < 64; d++) acc += rf[r*64 + d] * Wupd[(r*64 + d)*256 + o];
    out[(size_t)4*NC + r*256 + o] = acc;
}

__global__ void k_wsplit(const float* __restrict__ W_node, const float* __restrict__ Wres) {
    int idx = blockIdx.x * 256 + threadIdx.x;     // 4*512*256 = 524288
    int z = idx >> 17;
    int rem = idx & 131071;
    int k = rem >> 9;
    int n = rem & 511;
    int dt = 1 - (z & 1);
    float v = (n < 256) ? W_node[dt*65536 + k*256 + n]
                        : Wres[dt*65536 + k*256 + (n - 256)];
    __nv_bfloat16 hi = __float2bfloat16(v);
    __nv_bfloat16 lo = __float2bfloat16(v - __bfloat162float(hi));
    size_t o = (size_t)z*131072 + (size_t)n*256 + k;
    g_WTH[o] = hi;
    g_WTL[o] = lo;
}

// ---------------- CSR build ----------------
__global__ void k_zero_deg() {
    int i = blockIdx.x * 256 + threadIdx.x;
    if (i < 4*NN) g_DEG[i] = 0;
}

__global__ void k_hist(const int* __restrict__ d0, const int* __restrict__ d1,
                       const int* __restrict__ d2, const int* __restrict__ d3) {
    int i = blockIdx.x * 256 + threadIdx.x;
    if (i >= EE) return;
    int r = blockIdx.y;
    const int* dp = r==0?d0:(r==1?d1:(r==2?d2:d3));
    atomicAdd(&g_DEG[r*NN + dp[i]], 1);
}

// per-relation exclusive scan via warp shuffles (3 syncs per tile)
__global__ __launch_bounds__(1024) void k_scan() {
    int r = blockIdx.x;
    __shared__ int wsum[32];
    __shared__ int carry;
    int tid = threadIdx.x, lane = tid & 31, wid = tid >> 5;
    if (tid == 0) carry = 0;
    __syncthreads();
    for (int base = 0; base < NN; base += 1024) {
        int i = base + tid;
        int v = (i < NN) ? g_DEG[r*NN + i] : 0;
        int x = v;
        #pragma unroll
        for (int off = 1; off < 32; off <<= 1) {
            int t = __shfl_up_sync(0xffffffffu, x, off);
            if (lane >= off) x += t;
        }
        if (lane == 31) wsum[wid] = x;
        __syncthreads();
        if (wid == 0) {
            int y = wsum[lane];
            #pragma unroll
            for (int off = 1; off < 32; off <<= 1) {
                int t = __shfl_up_sync(0xffffffffu, y, off);
                if (lane >= off) y += t;
            }
            wsum[lane] = y;
        }
        __syncthreads();
        int cbase = carry;
        int woff = (wid == 0) ? 0 : wsum[wid - 1];
        int incl = cbase + woff + x;
        if (i < NN) {
            g_ROWPTR[r*(NN+1) + i + 1] = incl;
            g_WOFF[r*NN + i] = incl - v;
        }
        __syncthreads();
        if (tid == 0) carry = cbase + wsum[31];
        __syncthreads();
    }
    if (tid == 0) g_ROWPTR[r*(NN+1)] = 0;
}

__global__ void k_scatter(const int* __restrict__ s0, const int* __restrict__ s1,
                          const int* __restrict__ s2, const int* __restrict__ s3,
                          const int* __restrict__ d0, const int* __restrict__ d1,
                          const int* __restrict__ d2, const int* __restrict__ d3) {
    int i = blockIdx.x * 256 + threadIdx.x;
    if (i >= EE) return;
    int r = blockIdx.y;
    const int* sp = r==0?s0:(r==1?s1:(r==2?s2:s3));
    const int* dp = r==0?d0:(r==1?d1:(r==2?d2:d3));
    int pos = atomicAdd(&g_WOFF[r*NN + dp[i]], 1);
    g_ESRC[r*EE + pos] = sp[i];
}

// ---------------- tensor-core GEMM (3-term split-bf16) ----------------
#define GBM 128
#define GBN 128
#define APW 12
#define BPW 12
#define APLANE (128*APW)
#define BPLANE (128*BPW)
#define GSMEM_WORDS (4*APLANE + 4*BPLANE)
#define GSMEM_BYTES (GSMEM_WORDS*4)

__global__ __launch_bounds__(256) void k_gemm_bf16(const float* __restrict__ feats,
                                                   const float* __restrict__ bres) {
    extern __shared__ unsigned smw[];
    unsigned* As = smw;
    unsigned* Bs = smw + 4*APLANE;

    int z = blockIdx.z;
    const float* A = feats + (size_t)z * NC;
    const __nv_bfloat16* BTh = g_WTH + (size_t)z * 131072;
    const __nv_bfloat16* BTl = g_WTL + (size_t)z * 131072;
    int row0 = blockIdx.y * GBM;
    int col0 = blockIdx.x * GBN;
    int t = threadIdx.x;
    int lane = t & 31, wid = t >> 5;
    int wm = (wid & 1) * 64;
    int wn = (wid >> 1) * 32;
    int lr = lane >> 2;
    int lc = lane & 3;

    float4 av[2];
    uint4 bh, bl;
    int am[2], aksw[2];
    #pragma unroll
    for (int i = 0; i < 2; i++) {
        int idx = t + i*256;
        am[i] = idx >> 2;
        aksw[i] = (idx & 3) * 2;
    }
    int bn = t >> 1, bhalf = t & 1;

    float c[4][4][4];
    #pragma unroll
    for (int mi = 0; mi < 4; mi++)
        #pragma unroll
        for (int ni = 0; ni < 4; ni++)
            #pragma unroll
            for (int q = 0; q < 4; q++) c[mi][ni][q] = 0.f;

    auto doLoad = [&](int k0) {
        #pragma unroll
        for (int i = 0; i < 2; i++) {
            int gr = row0 + am[i];
            av[i] = (gr < NN) ? *(const float4*)(A + (size_t)gr*256 + k0 + aksw[i]*2)
                              : make_float4(0.f,0.f,0.f,0.f);
        }
        size_t bo = ((size_t)(col0 + bn))*256 + k0 + bhalf*8;
        bh = *(const uint4*)(BTh + bo);
        bl = *(const uint4*)(BTl + bo);
    };
    auto doStore = [&](int buf) {
        unsigned* ab = As + buf*2*APLANE;
        #pragma unroll
        for (int i = 0; i < 2; i++) {
            float4 v = av[i];
            __nv_bfloat16 hx = __float2bfloat16(v.x);
            __nv_bfloat16 hy = __float2bfloat16(v.y);
            __nv_bfloat16 hz = __float2bfloat16(v.z);
            __nv_bfloat16 hw = __float2bfloat16(v.w);
            unsigned hi0 = pack2(hx, hy), hi1 = pack2(hz, hw);
            unsigned lo0 = pack2(__float2bfloat16(v.x - __bfloat162float(hx)),
                                 __float2bfloat16(v.y - __bfloat162float(hy)));
            unsigned lo1 = pack2(__float2bfloat16(v.z - __bfloat162float(hz)),
                                 __float2bfloat16(v.w - __bfloat162float(hw)));
            int w = am[i]*APW + aksw[i];
            *(uint2*)(ab + w) = make_uint2(hi0, hi1);
            *(uint2*)(ab + APLANE + w) = make_uint2(lo0, lo1);
        }
        unsigned* bb = Bs + buf*2*BPLANE;
        int w = bn*BPW + bhalf*4;
        *(uint4*)(bb + w) = bh;
        *(uint4*)(bb + BPLANE + w) = bl;
    };

    doLoad(0);
    doStore(0);
    __syncthreads();

    #pragma unroll 1
    for (int kt = 0; kt < 16; kt++) {
        if (kt + 1 < 16) doLoad((kt + 1) * 16);
        int buf = kt & 1;
        const unsigned* Ab = As + buf*2*APLANE;
        const unsigned* Bb = Bs + buf*2*BPLANE;

        unsigned af[4][2][4];
        #pragma unroll
        for (int mi = 0; mi < 4; mi++) {
            int base = (wm + mi*16 + lr)*APW + lc;
            af[mi][0][0] = Ab[base];
            af[mi][0][1] = Ab[base + 8*APW];
            af[mi][0][2] = Ab[base + 4];
            af[mi][0][3] = Ab[base + 8*APW + 4];
            const unsigned* Al = Ab + APLANE;
            af[mi][1][0] = Al[base];
            af[mi][1][1] = Al[base + 8*APW];
            af[mi][1][2] = Al[base + 4];
            af[mi][1][3] = Al[base + 8*APW + 4];
        }
        unsigned bfr[4][2][2];
        #pragma unroll
        for (int ni = 0; ni < 4; ni++) {
            int base = (wn + ni*8 + lr)*BPW + lc;
            bfr[ni][0][0] = Bb[base];
            bfr[ni][0][1] = Bb[base + 4];
            const unsigned* Bl = Bb + BPLANE;
            bfr[ni][1][0] = Bl[base];
            bfr[ni][1][1] = Bl[base + 4];
        }
        #pragma unroll
        for (int mi = 0; mi < 4; mi++)
            #pragma unroll
            for (int ni = 0; ni < 4; ni++) {
                mma16(c[mi][ni], af[mi][0], bfr[ni][0]);
                mma16(c[mi][ni], af[mi][0], bfr[ni][1]);
                mma16(c[mi][ni], af[mi][1], bfr[ni][0]);
            }
        if (kt + 1 < 16) doStore((kt + 1) & 1);
        __syncthreads();
    }

    int dt = 1 - (z & 1);
    float om = 1.0f - g_ALPHA[dt];
    #pragma unroll
    for (int mi = 0; mi < 4; mi++) {
        int r0 = row0 + wm + mi*16 + lr;
        #pragma unroll
        for (int ni = 0; ni < 4; ni++) {
            int col = col0 + wn + ni*8 + 2*lc;
            if (col < 256) {
                if (r0 < NN)
                    *(float2*)(g_H + (size_t)z*NC + (size_t)r0*256 + col) =
                        make_float2(c[mi][ni][0], c[mi][ni][1]);
                if (r0 + 8 < NN)
                    *(float2*)(g_H + (size_t)z*NC + (size_t)(r0+8)*256 + col) =
                        make_float2(c[mi][ni][2], c[mi][ni][3]);
            } else {
                int c2 = col - 256;
                float b0 = bres[dt*256 + c2], b1 = bres[dt*256 + c2 + 1];
                if (r0 < NN)
                    *(float2*)(g_NR + (size_t)z*NC + (size_t)r0*256 + c2) =
                        make_float2(om*(c[mi][ni][0] + b0), om*(c[mi][ni][1] + b1));
                if (r0 + 8 < NN)
                    *(float2*)(g_NR + (size_t)z*NC + (size_t)(r0+8)*256 + c2) =
                        make_float2(om*(c[mi][ni][2] + b0), om*(c[mi][ni][3] + b1));
            }
        }
    }
}

// ---------------- per-node attention logits el/er ----------------
__global__ __launch_bounds__(256) void k_elr() {
    int t = blockIdx.y;
    int warp = threadIdx.x >> 5;
    int l = threadIdx.x & 31;
    int n = blockIdx.x * 8 + warp;
    if (n >= NN) return;
    const int REV[4] = {1, 0, 3, 2};
    int rr = REV[t];
    int k = l >> 2;
    int dbase = (l & 3) * 8;

    const float* hrow = g_H + t*NC + n*256 + l*8;
    float4 h0 = *(const float4*)hrow;
    float4 h1 = *(const float4*)(hrow + 4);
    float h[8] = {h0.x,h0.y,h0.z,h0.w,h1.x,h1.y,h1.z,h1.w};

    const float* aL = g_ATTN + rr*512 + k*64 + dbase;
    const float* aR = g_ATTN + t*512 + k*64 + 32 + dbase;
    float pl = 0.f, pr = 0.f;
    #pragma unroll
    for (int j = 0; j < 8; j++) { pl += h[j]*aL[j]; pr += h[j]*aR[j]; }
    pl += __shfl_xor_sync(0xffffffffu, pl, 1);
    pl += __shfl_xor_sync(0xffffffffu, pl, 2);
    pr += __shfl_xor_sync(0xffffffffu, pr, 1);
    pr += __shfl_xor_sync(0xffffffffu, pr, 2);
    if ((l & 3) == 0) {
        g_EL[rr*N8 + n*KH + k] = pl;
        g_ER[t*N8 + n*KH + k] = pr;
    }
}

// ---------------- fused conv + residual + cross-relation attention ----------------
// 8 warps / 4 nodes per block. warp (nloc, q): computes relation rel[q]'s conv+residual
// for node n into smem, then emits output row for relation rel[q].
__global__ __launch_bounds__(256) void k_convcross(const float* __restrict__ rel_attn,
                                                   float* __restrict__ out) {
    __shared__ float sh[4][2][256];
    int g = blockIdx.y;
    int warp = threadIdx.x >> 5;
    int lane = threadIdx.x & 31;
    int nloc = warp >> 1;
    int q = warp & 1;
    int n = blockIdx.x * 4 + nloc;
    const int REV[4] = {1, 0, 3, 2};
    int rel0 = (g == 0) ? 0 : 1;
    int rel1 = (g == 0) ? 2 : 3;
    int r = q ? rel1 : rel0;
    int dt = 1 - g;
    float alpha = g_ALPHA[dt];
    bool valid = (n < NN);

    if (valid) {
        int start = g_ROWPTR[r*(NN+1) + n];
        int end   = g_ROWPTR[r*(NN+1) + n + 1];
        float acc[8] = {0.f,0.f,0.f,0.f,0.f,0.f,0.f,0.f};
        if (start < end) {
            const int* esrc = g_ESRC + r*EE;
            const float* EL = g_EL + r*N8;
            int k = lane & 7, slot = lane >> 3;
            float er_k = g_ER[r*N8 + n*KH + k];

            // online softmax stats (4 edge-slots in parallel)
            float m = -INFINITY, zz = 0.f;
            for (int j0 = start; j0 < end; j0 += 4) {
                int j = j0 + slot;
                if (j < end) {
                    float e = leaky(EL[esrc[j]*KH + k] + er_k);
                    float nm = fmaxf(m, e);
                    zz = zz * __expf(m - nm) + __expf(e - nm);
                    m = nm;
                }
            }
            #pragma unroll
            for (int o2 = 8; o2 <= 16; o2 <<= 1) {
                float mo = __shfl_xor_sync(0xffffffffu, m, o2);
                float zo = __shfl_xor_sync(0xffffffffu, zz, o2);
                float nm = fmaxf(m, mo);
                float za = (zz > 0.f) ? zz * __expf(m - nm) : 0.f;
                float zb = (zo > 0.f) ? zo * __expf(mo - nm) : 0.f;
                zz = za + zb; m = nm;
            }
            float rz = 1.0f / zz;

            int k2 = lane >> 2;
            float er2 = __shfl_sync(0xffffffffu, er_k, k2);
            float m2  = __shfl_sync(0xffffffffu, m, k2);
            float rz2 = __shfl_sync(0xffffffffu, rz, k2);
            const float* Hp = g_H + (size_t)REV[r]*NC;

            // unrolled-by-2 accumulation: two independent gather chains in flight
            int j = start;
            for (; j + 1 < end; j += 2) {
                int s0 = esrc[j], s1 = esrc[j+1];
                float a0 = __expf(leaky(EL[s0*KH + k2] + er2) - m2) * rz2;
                float a1 = __expf(leaky(EL[s1*KH + k2] + er2) - m2) * rz2;
                const float* hp0 = Hp + (size_t)s0*256 + lane*8;
                const float* hp1 = Hp + (size_t)s1*256 + lane*8;
                float4 u0 = *(const float4*)hp0;
                float4 u1 = *(const float4*)(hp0 + 4);
                float4 v0 = *(const float4*)hp1;
                float4 v1 = *(const float4*)(hp1 + 4);
                acc[0] += a0*u0.x + a1*v0.x; acc[1] += a0*u0.y + a1*v0.y;
                acc[2] += a0*u0.z + a1*v0.z; acc[3] += a0*u0.w + a1*v0.w;
                acc[4] += a0*u1.x + a1*v1.x; acc[5] += a0*u1.y + a1*v1.y;
                acc[6] += a0*u1.z + a1*v1.z; acc[7] += a0*u1.w + a1*v1.w;
            }
            if (j < end) {
                int s0 = esrc[j];
                float a0 = __expf(leaky(EL[s0*KH + k2] + er2) - m2) * rz2;
                const float* hp0 = Hp + (size_t)s0*256 + lane*8;
                float4 u0 = *(const float4*)hp0;
                float4 u1 = *(const float4*)(hp0 + 4);
                acc[0] += a0*u0.x; acc[1] += a0*u0.y; acc[2] += a0*u0.z; acc[3] += a0*u0.w;
                acc[4] += a0*u1.x; acc[5] += a0*u1.y; acc[6] += a0*u1.z; acc[7] += a0*u1.w;
            }
        }
        const float* ip = g_NR + (size_t)r*NC + (size_t)n*256 + lane*8;
        float4 ia = *(const float4*)ip;
        float4 ib = *(const float4*)(ip + 4);
        float* sp = &sh[nloc][q][lane*8];
        sp[0] = alpha*fmaxf(acc[0],0.f) + ia.x;
        sp[1] = alpha*fmaxf(acc[1],0.f) + ia.y;
        sp[2] = alpha*fmaxf(acc[2],0.f) + ia.z;
        sp[3] = alpha*fmaxf(acc[3],0.f) + ia.w;
        sp[4] = alpha*fmaxf(acc[4],0.f) + ib.x;
        sp[5] = alpha*fmaxf(acc[5],0.f) + ib.y;
        sp[6] = alpha*fmaxf(acc[6],0.f) + ib.z;
        sp[7] = alpha*fmaxf(acc[7],0.f) + ib.w;
    }
    __syncthreads();
    if (!valid) return;

    // this warp emits output row for relation rel[q] of node n
    float h0[8], h1[8];
    {
        const float* p0 = &sh[nloc][0][lane*8];
        const float* p1 = &sh[nloc][1][lane*8];
        float4 a0 = *(const float4*)p0, a1 = *(const float4*)(p0+4);
        float4 b0 = *(const float4*)p1, b1 = *(const float4*)(p1+4);
        h0[0]=a0.x; h0[1]=a0.y; h0[2]=a0.z; h0[3]=a0.w;
        h0[4]=a1.x; h0[5]=a1.y; h0[6]=a1.z; h0[7]=a1.w;
        h1[0]=b0.x; h1[1]=b0.y; h1[2]=b0.z; h1[3]=b0.w;
        h1[4]=b1.x; h1[5]=b1.y; h1[6]=b1.z; h1[7]=b1.w;
    }
    int ro = q ? rel1 : rel0;
    const float* ra = rel_attn + ro*256 + lane*8;
    float s0 = 0.f, s1 = 0.f;
    #pragma unroll
    for (int j = 0; j < 8; j++) { s0 += h0[j]*ra[j]; s1 += h1[j]*ra[j]; }
    s0 += __shfl_xor_sync(0xffffffffu, s0, 1);
    s0 += __shfl_xor_sync(0xffffffffu, s0, 2);
    s1 += __shfl_xor_sync(0xffffffffu, s1, 1);
    s1 += __shfl_xor_sync(0xffffffffu, s1, 2);
    s0 = leaky(s0); s1 = leaky(s1);
    float mx = fmaxf(s0, s1);
    float w0 = __expf(s0 - mx), w1 = __expf(s1 - mx);
    float inv = 1.0f / (w0 + w1);
    w0 *= inv; w1 *= inv;
    float o[8];
    #pragma unroll
    for (int j = 0; j < 8; j++) o[j] = w0*h0[j] + w1*h1[j];
    float* op = out + (size_t)ro*NC + (size_t)n*256 + lane*8;
    *(float4*)op = make_float4(o[0],o[1],o[2],o[3]);
    *(float4*)(op+4) = make_float4(o[4],o[5],o[6],o[7]);
}

// ---------------- launch ----------------
extern "C" void kernel_launch(void* const* d_in, const int* in_sizes, int n_in,
                              void* d_out, int out_size) {
    const float* feats      = (const float*)d_in[0];
    const float* rel_feats  = (const float*)d_in[1];
    const int*   src_rates  = (const int*)d_in[2];
    const int*   dst_rates  = (const int*)d_in[3];
    const int*   src_clicks = (const int*)d_in[4];
    const int*   dst_clicks = (const int*)d_in[5];
    const float* W_node     = (const float*)d_in[6];
    const float* Wr         = (const float*)d_in[7];
    const float* Wres       = (const float*)d_in[8];
    const float* bres       = (const float*)d_in[9];
    const float* resw       = (const float*)d_in[10];
    const float* rel_attn   = (const float*)d_in[11];
    const float* Wupd       = (const float*)d_in[12];
    const float* bupd       = (const float*)d_in[13];
    float* out = (float*)d_out;

    const int* S0 = src_rates;  const int* S1 = dst_rates;
    const int* S2 = src_clicks; const int* S3 = dst_clicks;
    const int* D0 = dst_rates;  const int* D1 = src_rates;
    const int* D2 = dst_clicks; const int* D3 = src_clicks;

    static int smem_set = 0;
    if (!smem_set) {
        cudaFuncSetAttribute(k_gemm_bf16, cudaFuncAttributeMaxDynamicSharedMemorySize, GSMEM_BYTES);
        smem_set = 1;
    }

    // setup + CSR build
    k_attn<<<4, 512>>>(rel_feats, Wr);
    k_alpha<<<1, 32>>>(resw);
    k_relout<<<4, 256>>>(rel_feats, Wupd, bupd, out);
    k_wsplit<<<2048, 256>>>(W_node, Wres);
    k_zero_deg<<<(4*NN + 255)/256, 256>>>();
    k_hist<<<dim3((EE + 255)/256, 4), 256>>>(D0, D1, D2, D3);
    k_scan<<<4, 1024>>>();
    k_scatter<<<dim3((EE + 255)/256, 4), 256>>>(S0,S1,S2,S3, D0,D1,D2,D3);

    // projections
    dim3 ggrid(512/GBN, (NN + GBM - 1)/GBM, 4);
    k_gemm_bf16<<<ggrid, 256, GSMEM_BYTES>>>(feats, bres);

    // attention + fused conv/cross
    k_elr<<<dim3(NN/8, 4), 256>>>();
    k_convcross<<<dim3((NN + 3)/4, 2), 256>>>(rel_attn, out);
}

// round 8
// speedup vs baseline: 3.5874x; 1.0443x over previous
#include <cuda_runtime.h>
#include <cuda_bf16.h>
#include <math.h>
#include <cstdint>

// Problem constants
#define NN 50000
#define EE 300000
#define CC 256            // K*D_OUT
#define NC (NN*CC)        // 12,800,000
#define KH 8
#define N8 (NN*KH)
#define SLOPE 0.2f

// ---------------- scratch (static device allocations) ----------------
__device__ float g_H[4*NC];       // node projections
__device__ float g_NR[4*NC];      // (1-alpha)*(feats[r]@Wres + bres)
__device__ float g_EL[4*N8];
__device__ float g_ER[4*N8];
__device__ float g_ATTN[4*512];
__device__ __nv_bfloat16 g_WTH[4*512*256];  // transposed [z][n][k] split-bf16 hi
__device__ __nv_bfloat16 g_WTL[4*512*256];  // lo
__device__ float g_ALPHA[2];

// CSR
__device__ int g_DEG[4*NN];
__device__ int g_ROWPTR[4*(NN+1)];
__device__ int g_WOFF[4*NN];
__device__ int g_ESRC[4*EE];

__device__ __forceinline__ float leaky(float x) { return x >= 0.f ? x : SLOPE*x; }

__device__ __forceinline__ void mma16(float* c, const unsigned* a, const unsigned* b) {
    asm volatile("mma.sync.aligned.m16n8k16.row.col.f32.bf16.bf16.f32 "
        "{%0,%1,%2,%3}, {%4,%5,%6,%7}, {%8,%9}, {%0,%1,%2,%3};"
        : "+f"(c[0]), "+f"(c[1]), "+f"(c[2]), "+f"(c[3])
        : "r"(a[0]), "r"(a[1]), "r"(a[2]), "r"(a[3]), "r"(b[0]), "r"(b[1]));
}

__device__ __forceinline__ unsigned pack2(__nv_bfloat16 a, __nv_bfloat16 b) {
    return (unsigned)__bfloat16_as_ushort(a) | ((unsigned)__bfloat16_as_ushort(b) << 16);
}

__device__ __forceinline__ uint32_t smem_u32(const void* p) {
    uint32_t a;
    asm("{ .reg .u64 t; cvta.to.shared.u64 t, %1; cvt.u32.u64 %0, t; }" : "=r"(a) : "l"(p));
    return a;
}

__device__ __forceinline__ void ldsm_x4(unsigned* r, uint32_t addr) {
    asm volatile("ldmatrix.sync.aligned.m8n8.x4.shared.b16 {%0,%1,%2,%3}, [%4];"
        : "=r"(r[0]), "=r"(r[1]), "=r"(r[2]), "=r"(r[3]) : "r"(addr));
}
__device__ __forceinline__ void ldsm_x2(unsigned* r, uint32_t addr) {
    asm volatile("ldmatrix.sync.aligned.m8n8.x2.shared.b16 {%0,%1}, [%2];"
        : "=r"(r[0]), "=r"(r[1]) : "r"(addr));
}

#define CP_ASYNC16(dst, src) \
    asm volatile("cp.async.ca.shared.global [%0], [%1], 16;" :: "r"(dst), "l"(src) : "memory")
#define CP_COMMIT() asm volatile("cp.async.commit_group;" ::: "memory")
#define CP_WAIT0()  asm volatile("cp.async.wait_group 0;" ::: "memory")

// ---------------- tiny setup kernels ----------------
__global__ void k_attn(const float* __restrict__ rf, const float* __restrict__ Wr) {
    int r = blockIdx.x;
    int j = threadIdx.x;
    float acc = 0.f;
    #pragma unroll 8
    for (int d = 0; d < 64; d++) acc += rf[r*64 + d] * Wr[(r*64 + d)*512 + j];
    g_ATTN[r*512 + j] = acc;
}

__global__ void k_alpha(const float* __restrict__ resw) {
    int t = threadIdx.x;
    if (t < 2) g_ALPHA[t] = 1.0f / (1.0f + expf(-resw[t]));
}

__global__ void k_relout(const float* __restrict__ rf, const float* __restrict__ Wupd,
                         const float* __restrict__ bupd, float* __restrict__ out) {
    int r = blockIdx.x;
    int o = threadIdx.x;
    float acc = bupd[r*256 + o];
    #pragma unroll 8
    for (int d = 0; d < 64; d++) acc += rf[r*64 + d] * Wupd[(r*64 + d)*256 + o];
    out[(size_t)4*NC + r*256 + o] = acc;
}

__global__ void k_wsplit(const float* __restrict__ W_node, const float* __restrict__ Wres) {
    int idx = blockIdx.x * 256 + threadIdx.x;     // 4*512*256 = 524288
    int z = idx >> 17;
    int rem = idx & 131071;
    int k = rem >> 9;
    int n = rem & 511;
    int dt = 1 - (z & 1);
    float v = (n < 256) ? W_node[dt*65536 + k*256 + n]
                        : Wres[dt*65536 + k*256 + (n - 256)];
    __nv_bfloat16 hi = __float2bfloat16(v);
    __nv_bfloat16 lo = __float2bfloat16(v - __bfloat162float(hi));
    size_t o = (size_t)z*131072 + (size_t)n*256 + k;
    g_WTH[o] = hi;
    g_WTL[o] = lo;
}

// ---------------- CSR build ----------------
__global__ void k_zero_deg() {
    int i = blockIdx.x * 256 + threadIdx.x;
    if (i < 4*NN) g_DEG[i] = 0;
}

__global__ void k_hist(const int* __restrict__ d0, const int* __restrict__ d1,
                       const int* __restrict__ d2, const int* __restrict__ d3) {
    int i = blockIdx.x * 256 + threadIdx.x;
    if (i >= EE) return;
    int r = blockIdx.y;
    const int* dp = r==0?d0:(r==1?d1:(r==2?d2:d3));
    atomicAdd(&g_DEG[r*NN + dp[i]], 1);
}

__global__ __launch_bounds__(1024) void k_scan() {
    int r = blockIdx.x;
    __shared__ int wsum[32];
    __shared__ int carry;
    int tid = threadIdx.x, lane = tid & 31, wid = tid >> 5;
    if (tid == 0) carry = 0;
    __syncthreads();
    for (int base = 0; base < NN; base += 1024) {
        int i = base + tid;
        int v = (i < NN) ? g_DEG[r*NN + i] : 0;
        int x = v;
        #pragma unroll
        for (int off = 1; off < 32; off <<= 1) {
            int t = __shfl_up_sync(0xffffffffu, x, off);
            if (lane >= off) x += t;
        }
        if (lane == 31) wsum[wid] = x;
        __syncthreads();
        if (wid == 0) {
            int y = wsum[lane];
            #pragma unroll
            for (int off = 1; off < 32; off <<= 1) {
                int t = __shfl_up_sync(0xffffffffu, y, off);
                if (lane >= off) y += t;
            }
            wsum[lane] = y;
        }
        __syncthreads();
        int cbase = carry;
        int woff = (wid == 0) ? 0 : wsum[wid - 1];
        int incl = cbase + woff + x;
        if (i < NN) {
            g_ROWPTR[r*(NN+1) + i + 1] = incl;
            g_WOFF[r*NN + i] = incl - v;
        }
        __syncthreads();
        if (tid == 0) carry = cbase + wsum[31];
        __syncthreads();
    }
    if (tid == 0) g_ROWPTR[r*(NN+1)] = 0;
}

__global__ void k_scatter(const int* __restrict__ s0, const int* __restrict__ s1,
                          const int* __restrict__ s2, const int* __restrict__ s3,
                          const int* __restrict__ d0, const int* __restrict__ d1,
                          const int* __restrict__ d2, const int* __restrict__ d3) {
    int i = blockIdx.x * 256 + threadIdx.x;
    if (i >= EE) return;
    int r = blockIdx.y;
    const int* sp = r==0?s0:(r==1?s1:(r==2?s2:s3));
    const int* dp = r==0?d0:(r==1?d1:(r==2?d2:d3));
    int pos = atomicAdd(&g_WOFF[r*NN + dp[i]], 1);
    g_ESRC[r*EE + pos] = sp[i];
}

// ---------------- tensor-core GEMM (3-term split-bf16) ----------------
// C[z] = feats[z] @ WCAT[z]; M=50000, N=512, K=256.
// CTA 128x128, 256 threads (8 warps, 2x4 -> warp tile 64x32), BK=16, double-buffered.
// A: LDG fp32 -> split bf16 -> STS. B: cp.async (pre-split bf16 in gmem).
// Fragments loaded with ldmatrix (conflict-free via pitch-12 rows).
#define GBM 128
#define GBN 128
#define APW 12
#define BPW 12
#define APLANE (128*APW)
#define BPLANE (128*BPW)
#define GSMEM_WORDS (4*APLANE + 4*BPLANE)
#define GSMEM_BYTES (GSMEM_WORDS*4)

__global__ __launch_bounds__(256) void k_gemm_bf16(const float* __restrict__ feats,
                                                   const float* __restrict__ bres) {
    extern __shared__ unsigned smw[];
    unsigned* As = smw;
    unsigned* Bs = smw + 4*APLANE;

    int z = blockIdx.z;
    const float* A = feats + (size_t)z * NC;
    const __nv_bfloat16* BTh = g_WTH + (size_t)z * 131072;
    const __nv_bfloat16* BTl = g_WTL + (size_t)z * 131072;
    int row0 = blockIdx.y * GBM;
    int col0 = blockIdx.x * GBN;
    int t = threadIdx.x;
    int lane = t & 31, wid = t >> 5;
    int wm = (wid & 1) * 64;
    int wn = (wid >> 1) * 32;

    uint32_t a_u32 = smem_u32(As);
    uint32_t b_u32 = smem_u32(Bs);

    // ldmatrix lane addressing
    int a_row_in = (lane & 7) + ((lane >> 3) & 1) * 8;  // 0..15
    int a_sec = lane >> 4;                              // 0..1 (k section)
    int b_row_in = lane & 7;
    int b_sec = (lane >> 3) & 1;

    // staging indices
    float4 av[2];
    int am[2], aksw[2];
    #pragma unroll
    for (int i = 0; i < 2; i++) {
        int idx = t + i*256;
        am[i] = idx >> 2;
        aksw[i] = (idx & 3) * 2;
    }
    int bn = t >> 1, bhalf = t & 1;

    float c[4][4][4];
    #pragma unroll
    for (int mi = 0; mi < 4; mi++)
        #pragma unroll
        for (int ni = 0; ni < 4; ni++)
            #pragma unroll
            for (int q = 0; q < 4; q++) c[mi][ni][q] = 0.f;

    auto loadA = [&](int k0) {
        #pragma unroll
        for (int i = 0; i < 2; i++) {
            int gr = row0 + am[i];
            av[i] = (gr < NN) ? *(const float4*)(A + (size_t)gr*256 + k0 + aksw[i]*2)
                              : make_float4(0.f,0.f,0.f,0.f);
        }
    };
    auto cpB = [&](int k0, int buf) {
        size_t bo = ((size_t)(col0 + bn))*256 + k0 + bhalf*8;
        uint32_t dst = b_u32 + (uint32_t)(buf*2*BPLANE + bn*BPW + bhalf*4)*4;
        CP_ASYNC16(dst, (const void*)(BTh + bo));
        CP_ASYNC16(dst + (uint32_t)BPLANE*4, (const void*)(BTl + bo));
    };
    auto storeA = [&](int buf) {
        unsigned* ab = As + buf*2*APLANE;
        #pragma unroll
        for (int i = 0; i < 2; i++) {
            float4 v = av[i];
            __nv_bfloat16 hx = __float2bfloat16(v.x);
            __nv_bfloat16 hy = __float2bfloat16(v.y);
            __nv_bfloat16 hz = __float2bfloat16(v.z);
            __nv_bfloat16 hw = __float2bfloat16(v.w);
            unsigned hi0 = pack2(hx, hy), hi1 = pack2(hz, hw);
            unsigned lo0 = pack2(__float2bfloat16(v.x - __bfloat162float(hx)),
                                 __float2bfloat16(v.y - __bfloat162float(hy)));
            unsigned lo1 = pack2(__float2bfloat16(v.z - __bfloat162float(hz)),
                                 __float2bfloat16(v.w - __bfloat162float(hw)));
            int w = am[i]*APW + aksw[i];
            *(uint2*)(ab + w) = make_uint2(hi0, hi1);
            *(uint2*)(ab + APLANE + w) = make_uint2(lo0, lo1);
        }
    };

    loadA(0);
    cpB(0, 0);
    CP_COMMIT();
    storeA(0);
    CP_WAIT0();
    __syncthreads();

    #pragma unroll 1
    for (int kt = 0; kt < 16; kt++) {
        if (kt + 1 < 16) {
            loadA((kt + 1) * 16);
            cpB((kt + 1) * 16, (kt + 1) & 1);
            CP_COMMIT();
        }
        int buf = kt & 1;
        uint32_t aB = a_u32 + (uint32_t)(buf*2*APLANE)*4;
        uint32_t bB = b_u32 + (uint32_t)(buf*2*BPLANE)*4;

        unsigned af[4][2][4];
        #pragma unroll
        for (int mi = 0; mi < 4; mi++) {
            uint32_t addr = aB + (uint32_t)((wm + mi*16 + a_row_in)*APW)*4 + a_sec*16;
            ldsm_x4(af[mi][0], addr);
            ldsm_x4(af[mi][1], addr + (uint32_t)APLANE*4);
        }
        unsigned bfr[4][2][2];
        #pragma unroll
        for (int ni = 0; ni < 4; ni++) {
            uint32_t addr = bB + (uint32_t)((wn + ni*8 + b_row_in)*BPW)*4 + b_sec*16;
            ldsm_x2(bfr[ni][0], addr);
            ldsm_x2(bfr[ni][1], addr + (uint32_t)BPLANE*4);
        }
        #pragma unroll
        for (int mi = 0; mi < 4; mi++)
            #pragma unroll
            for (int ni = 0; ni < 4; ni++) {
                mma16(c[mi][ni], af[mi][0], bfr[ni][0]);
                mma16(c[mi][ni], af[mi][0], bfr[ni][1]);
                mma16(c[mi][ni], af[mi][1], bfr[ni][0]);
            }
        if (kt + 1 < 16) storeA((kt + 1) & 1);
        CP_WAIT0();
        __syncthreads();
    }

    int lr = lane >> 2;
    int lc = lane & 3;
    int dt = 1 - (z & 1);
    float om = 1.0f - g_ALPHA[dt];
    #pragma unroll
    for (int mi = 0; mi < 4; mi++) {
        int r0 = row0 + wm + mi*16 + lr;
        #pragma unroll
        for (int ni = 0; ni < 4; ni++) {
            int col = col0 + wn + ni*8 + 2*lc;
            if (col < 256) {
                if (r0 < NN)
                    *(float2*)(g_H + (size_t)z*NC + (size_t)r0*256 + col) =
                        make_float2(c[mi][ni][0], c[mi][ni][1]);
                if (r0 + 8 < NN)
                    *(float2*)(g_H + (size_t)z*NC + (size_t)(r0+8)*256 + col) =
                        make_float2(c[mi][ni][2], c[mi][ni][3]);
            } else {
                int c2 = col - 256;
                float b0 = bres[dt*256 + c2], b1 = bres[dt*256 + c2 + 1];
                if (r0 < NN)
                    *(float2*)(g_NR + (size_t)z*NC + (size_t)r0*256 + c2) =
                        make_float2(om*(c[mi][ni][0] + b0), om*(c[mi][ni][1] + b1));
                if (r0 + 8 < NN)
                    *(float2*)(g_NR + (size_t)z*NC + (size_t)(r0+8)*256 + c2) =
                        make_float2(om*(c[mi][ni][2] + b0), om*(c[mi][ni][3] + b1));
            }
        }
    }
}

// ---------------- per-node attention logits el/er ----------------
__global__ __launch_bounds__(256) void k_elr() {
    int t = blockIdx.y;
    int warp = threadIdx.x >> 5;
    int l = threadIdx.x & 31;
    int n = blockIdx.x * 8 + warp;
    if (n >= NN) return;
    const int REV[4] = {1, 0, 3, 2};
    int rr = REV[t];
    int k = l >> 2;
    int dbase = (l & 3) * 8;

    const float* hrow = g_H + t*NC + n*256 + l*8;
    float4 h0 = *(const float4*)hrow;
    float4 h1 = *(const float4*)(hrow + 4);
    float h[8] = {h0.x,h0.y,h0.z,h0.w,h1.x,h1.y,h1.z,h1.w};

    const float* aL = g_ATTN + rr*512 + k*64 + dbase;
    const float* aR = g_ATTN + t*512 + k*64 + 32 + dbase;
    float pl = 0.f, pr = 0.f;
    #pragma unroll
    for (int j = 0; j < 8; j++) { pl += h[j]*aL[j]; pr += h[j]*aR[j]; }
    pl += __shfl_xor_sync(0xffffffffu, pl, 1);
    pl += __shfl_xor_sync(0xffffffffu, pl, 2);
    pr += __shfl_xor_sync(0xffffffffu, pr, 1);
    pr += __shfl_xor_sync(0xffffffffu, pr, 2);
    if ((l & 3) == 0) {
        g_EL[rr*N8 + n*KH + k] = pl;
        g_ER[t*N8 + n*KH + k] = pr;
    }
}

// ---------------- fused conv + residual + cross-relation attention ----------------
__global__ __launch_bounds__(256) void k_convcross(const float* __restrict__ rel_attn,
                                                   float* __restrict__ out) {
    __shared__ float sh[4][2][256];
    int g = blockIdx.y;
    int warp = threadIdx.x >> 5;
    int lane = threadIdx.x & 31;
    int nloc = warp >> 1;
    int q = warp & 1;
    int n = blockIdx.x * 4 + nloc;
    const int REV[4] = {1, 0, 3, 2};
    int rel0 = (g == 0) ? 0 : 1;
    int rel1 = (g == 0) ? 2 : 3;
    int r = q ? rel1 : rel0;
    int dt = 1 - g;
    float alpha = g_ALPHA[dt];
    bool valid = (n < NN);

    if (valid) {
        int start = g_ROWPTR[r*(NN+1) + n];
        int end   = g_ROWPTR[r*(NN+1) + n + 1];
        float acc[8] = {0.f,0.f,0.f,0.f,0.f,0.f,0.f,0.f};
        if (start < end) {
            const int* esrc = g_ESRC + r*EE;
            const float* EL = g_EL + r*N8;
            int k = lane & 7, slot = lane >> 3;
            float er_k = g_ER[r*N8 + n*KH + k];

            float m = -INFINITY, zz = 0.f;
            for (int j0 = start; j0 < end; j0 += 4) {
                int j = j0 + slot;
                if (j < end) {
                    float e = leaky(EL[esrc[j]*KH + k] + er_k);
                    float nm = fmaxf(m, e);
                    zz = zz * __expf(m - nm) + __expf(e - nm);
                    m = nm;
                }
            }
            #pragma unroll
            for (int o2 = 8; o2 <= 16; o2 <<= 1) {
                float mo = __shfl_xor_sync(0xffffffffu, m, o2);
                float zo = __shfl_xor_sync(0xffffffffu, zz, o2);
                float nm = fmaxf(m, mo);
                float za = (zz > 0.f) ? zz * __expf(m - nm) : 0.f;
                float zb = (zo > 0.f) ? zo * __expf(mo - nm) : 0.f;
                zz = za + zb; m = nm;
            }
            float rz = 1.0f / zz;

            int k2 = lane >> 2;
            float er2 = __shfl_sync(0xffffffffu, er_k, k2);
            float m2  = __shfl_sync(0xffffffffu, m, k2);
            float rz2 = __shfl_sync(0xffffffffu, rz, k2);
            const float* Hp = g_H + (size_t)REV[r]*NC;

            int j = start;
            for (; j + 1 < end; j += 2) {
                int s0 = esrc[j], s1 = esrc[j+1];
                float a0 = __expf(leaky(EL[s0*KH + k2] + er2) - m2) * rz2;
                float a1 = __expf(leaky(EL[s1*KH + k2] + er2) - m2) * rz2;
                const float* hp0 = Hp + (size_t)s0*256 + lane*8;
                const float* hp1 = Hp + (size_t)s1*256 + lane*8;
                float4 u0 = *(const float4*)hp0;
                float4 u1 = *(const float4*)(hp0 + 4);
                float4 v0 = *(const float4*)hp1;
                float4 v1 = *(const float4*)(hp1 + 4);
                acc[0] += a0*u0.x + a1*v0.x; acc[1] += a0*u0.y + a1*v0.y;
                acc[2] += a0*u0.z + a1*v0.z; acc[3] += a0*u0.w + a1*v0.w;
                acc[4] += a0*u1.x + a1*v1.x; acc[5] += a0*u1.y + a1*v1.y;
                acc[6] += a0*u1.z + a1*v1.z; acc[7] += a0*u1.w + a1*v1.w;
            }
            if (j < end) {
                int s0 = esrc[j];
                float a0 = __expf(leaky(EL[s0*KH + k2] + er2) - m2) * rz2;
                const float* hp0 = Hp + (size_t)s0*256 + lane*8;
                float4 u0 = *(const float4*)hp0;
                float4 u1 = *(const float4*)(hp0 + 4);
                acc[0] += a0*u0.x; acc[1] += a0*u0.y; acc[2] += a0*u0.z; acc[3] += a0*u0.w;
                acc[4] += a0*u1.x; acc[5] += a0*u1.y; acc[6] += a0*u1.z; acc[7] += a0*u1.w;
            }
        }
        const float* ip = g_NR + (size_t)r*NC + (size_t)n*256 + lane*8;
        float4 ia = *(const float4*)ip;
        float4 ib = *(const float4*)(ip + 4);
        float* sp = &sh[nloc][q][lane*8];
        sp[0] = alpha*fmaxf(acc[0],0.f) + ia.x;
        sp[1] = alpha*fmaxf(acc[1],0.f) + ia.y;
        sp[2] = alpha*fmaxf(acc[2],0.f) + ia.z;
        sp[3] = alpha*fmaxf(acc[3],0.f) + ia.w;
        sp[4] = alpha*fmaxf(acc[4],0.f) + ib.x;
        sp[5] = alpha*fmaxf(acc[5],0.f) + ib.y;
        sp[6] = alpha*fmaxf(acc[6],0.f) + ib.z;
        sp[7] = alpha*fmaxf(acc[7],0.f) + ib.w;
    }
    __syncthreads();
    if (!valid) return;

    float h0[8], h1[8];
    {
        const float* p0 = &sh[nloc][0][lane*8];
        const float* p1 = &sh[nloc][1][lane*8];
        float4 a0 = *(const float4*)p0, a1 = *(const float4*)(p0+4);
        float4 b0 = *(const float4*)p1, b1 = *(const float4*)(p1+4);
        h0[0]=a0.x; h0[1]=a0.y; h0[2]=a0.z; h0[3]=a0.w;
        h0[4]=a1.x; h0[5]=a1.y; h0[6]=a1.z; h0[7]=a1.w;
        h1[0]=b0.x; h1[1]=b0.y; h1[2]=b0.z; h1[3]=b0.w;
        h1[4]=b1.x; h1[5]=b1.y; h1[6]=b1.z; h1[7]=b1.w;
    }
    int ro = q ? rel1 : rel0;
    const float* ra = rel_attn + ro*256 + lane*8;
    float s0 = 0.f, s1 = 0.f;
    #pragma unroll
    for (int j = 0; j < 8; j++) { s0 += h0[j]*ra[j]; s1 += h1[j]*ra[j]; }
    s0 += __shfl_xor_sync(0xffffffffu, s0, 1);
    s0 += __shfl_xor_sync(0xffffffffu, s0, 2);
    s1 += __shfl_xor_sync(0xffffffffu, s1, 1);
    s1 += __shfl_xor_sync(0xffffffffu, s1, 2);
    s0 = leaky(s0); s1 = leaky(s1);
    float mx = fmaxf(s0, s1);
    float w0 = __expf(s0 - mx), w1 = __expf(s1 - mx);
    float inv = 1.0f / (w0 + w1);
    w0 *= inv; w1 *= inv;
    float o[8];
    #pragma unroll
    for (int j = 0; j < 8; j++) o[j] = w0*h0[j] + w1*h1[j];
    float* op = out + (size_t)ro*NC + (size_t)n*256 + lane*8;
    *(float4*)op = make_float4(o[0],o[1],o[2],o[3]);
    *(float4*)(op+4) = make_float4(o[4],o[5],o[6],o[7]);
}

// ---------------- launch ----------------
extern "C" void kernel_launch(void* const* d_in, const int* in_sizes, int n_in,
                              void* d_out, int out_size) {
    const float* feats      = (const float*)d_in[0];
    const float* rel_feats  = (const float*)d_in[1];
    const int*   src_rates  = (const int*)d_in[2];
    const int*   dst_rates  = (const int*)d_in[3];
    const int*   src_clicks = (const int*)d_in[4];
    const int*   dst_clicks = (const int*)d_in[5];
    const float* W_node     = (const float*)d_in[6];
    const float* Wr         = (const float*)d_in[7];
    const float* Wres       = (const float*)d_in[8];
    const float* bres       = (const float*)d_in[9];
    const float* resw       = (const float*)d_in[10];
    const float* rel_attn   = (const float*)d_in[11];
    const float* Wupd       = (const float*)d_in[12];
    const float* bupd       = (const float*)d_in[13];
    float* out = (float*)d_out;

    const int* S0 = src_rates;  const int* S1 = dst_rates;
    const int* S2 = src_clicks; const int* S3 = dst_clicks;
    const int* D0 = dst_rates;  const int* D1 = src_rates;
    const int* D2 = dst_clicks; const int* D3 = src_clicks;

    static int smem_set = 0;
    if (!smem_set) {
        cudaFuncSetAttribute(k_gemm_bf16, cudaFuncAttributeMaxDynamicSharedMemorySize, GSMEM_BYTES);
        smem_set = 1;
    }

    // order: k_gemm_bf16 in the profiled slot (#4)
    k_wsplit<<<2048, 256>>>(W_node, Wres);
    k_alpha<<<1, 32>>>(resw);
    k_attn<<<4, 512>>>(rel_feats, Wr);

    dim3 ggrid(512/GBN, (NN + GBM - 1)/GBM, 4);
    k_gemm_bf16<<<ggrid, 256, GSMEM_BYTES>>>(feats, bres);

    k_relout<<<4, 256>>>(rel_feats, Wupd, bupd, out);
    k_zero_deg<<<(4*NN + 255)/256, 256>>>();
    k_hist<<<dim3((EE + 255)/256, 4), 256>>>(D0, D1, D2, D3);
    k_scan<<<4, 1024>>>();
    k_scatter<<<dim3((EE + 255)/256, 4), 256>>>(S0,S1,S2,S3, D0,D1,D2,D3);

    k_elr<<<dim3(NN/8, 4), 256>>>();
    k_convcross<<<dim3((NN + 3)/4, 2), 256>>>(rel_attn, out);
}